// round 7
// baseline (speedup 1.0000x reference)
#include <cuda_runtime.h>
#include <cuda_bf16.h>
#include <cuda_fp16.h>
#include <math.h>
#include <stdint.h>

// ---------------- problem constants ----------------
#define BB   2
#define NN   10000
#define NT   20000           // BB*NN nodes
#define EE   160000          // edges per graph
#define EB   320000          // BB*EE batched edges
#define ET   340000          // EB + NT self loops
#define FIN  256
#define HID  256
#define HH   2
#define F1   512             // HH*HID
#define FOUT 256
#define NEG_SLOPE 0.2f

// ---------------- device scratch ----------------
__device__ __half g_xh1[(size_t)NT * F1];            // fp16 xw1 for agg1 gathers
__device__ __half g_xh2[(size_t)NT * FOUT];          // fp16 xw2 for agg2 gathers
__device__ __nv_bfloat16 g_A1[(size_t)NT * 512];     // [x_hi(256) | x_lo(256)]
__device__ __nv_bfloat16 g_A2[(size_t)NT * 1024];    // [h_hi(512) | h_lo(512)]
__device__ __nv_bfloat16 g_Wt1[(size_t)512 * 512];   // W1^T: [n=512][hi(256)|lo(256)]
__device__ __nv_bfloat16 g_Wt2[(size_t)256 * 1024];  // W2^T: [n=256][hi(512)|lo(512)]
__device__ float g_pas[8 * NT];                      // partial alpha_src per n-tile-half
__device__ float g_pad[8 * NT];                      // partial alpha_dst per n-tile-half
__device__ float g_as1[NT * HH];
__device__ float g_ad1[NT * HH];
__device__ float g_as2[NT];
__device__ float g_ad2[NT];
__device__ int   g_cnt[NT + 1];
__device__ int   g_off[NT + 1];
__device__ int   g_srcidx[ET];

// ---------------- helpers ----------------
__device__ __forceinline__ uint32_t smem_u32(const void* p) {
    return (uint32_t)__cvta_generic_to_shared(p);
}
__device__ __forceinline__ void cp16(uint32_t dst, const void* src, int src_sz) {
    asm volatile("cp.async.cg.shared.global [%0], [%1], 16, %2;"
                 :: "r"(dst), "l"(src), "r"(src_sz) : "memory");
}
__device__ __forceinline__ void cp_commit() {
    asm volatile("cp.async.commit_group;" ::: "memory");
}
template <int N>
__device__ __forceinline__ void cp_wait() {
    asm volatile("cp.async.wait_group %0;" :: "n"(N) : "memory");
}
__device__ __forceinline__ void ldm4(uint32_t* r, uint32_t addr) {
    asm volatile("ldmatrix.sync.aligned.m8n8.x4.shared.b16 {%0,%1,%2,%3}, [%4];"
                 : "=r"(r[0]), "=r"(r[1]), "=r"(r[2]), "=r"(r[3]) : "r"(addr));
}
__device__ __forceinline__ void mma16816(float* c, const uint32_t* a, const uint32_t* b) {
    asm volatile(
        "mma.sync.aligned.m16n8k16.row.col.f32.bf16.bf16.f32 "
        "{%0,%1,%2,%3}, {%4,%5,%6,%7}, {%8,%9}, {%0,%1,%2,%3};"
        : "+f"(c[0]), "+f"(c[1]), "+f"(c[2]), "+f"(c[3])
        : "r"(a[0]), "r"(a[1]), "r"(a[2]), "r"(a[3]), "r"(b[0]), "r"(b[1]));
}
__device__ __forceinline__ void split_bf16(float f, __nv_bfloat16& hi, __nv_bfloat16& lo) {
    hi = __float2bfloat16(f);
    lo = __float2bfloat16(f - __bfloat162float(hi));
}
// XOR swizzle: 64B rows, chunk' = chunk ^ ((row>>1)&3); conflict-free ldmatrix, 16B-aligned
__device__ __forceinline__ uint32_t swz(int row, int cByte) {
    return (uint32_t)(row * 64 + (cByte ^ ((((row >> 1) & 3)) << 4)));
}

// ---------------- bf16x3 mma.sync GEMM, 3-stage cp.async, BKr=32 ----------------
// Output: fp16 Ch only. Alpha partials (xw·attS, xw·attD) written per (row, n-half).
#define BM 128
#define BN 128
#define BKr 32
#define TILE_B (128 * 64)            // 8192 bytes per tile (swizzled, no pad)
#define STAGE_B (4 * TILE_B)         // Ah, Al, Bh, Bl = 32768
#define NSTG 3
#define GEMM_SMEM (NSTG * STAGE_B)   // 98304 bytes

__global__ __launch_bounds__(256, 2)
void gemm_kernel(const __nv_bfloat16* __restrict__ A,
                 const __nv_bfloat16* __restrict__ Bt,
                 __half* __restrict__ Ch,
                 const float* __restrict__ attS, const float* __restrict__ attD,
                 float* __restrict__ pAS, float* __restrict__ pAD,
                 int M, int N, int K) {
    extern __shared__ char sm[];
    const int tid = threadIdx.x;
    const int lane = tid & 31;
    const int wid = tid >> 5;
    const int wm = wid & 3;          // 4 warps over M (32 rows each)
    const int wn = wid >> 2;         // 2 warps over N (64 cols each)
    const int m0 = blockIdx.y * BM;
    const int n0 = blockIdx.x * BN;
    const int K2 = 2 * K;
    const uint32_t sbase = smem_u32(sm);

    float acc[2][8][4];
#pragma unroll
    for (int i = 0; i < 2; i++)
#pragma unroll
        for (int j = 0; j < 8; j++)
#pragma unroll
            for (int t = 0; t < 4; t++) acc[i][j][t] = 0.f;

    // loader
    const int lrow = tid >> 1;
    const int cb = (tid & 1) * 32;
    const uint32_t sw0 = swz(lrow, cb);
    const uint32_t sw1 = swz(lrow, cb + 16);
    const int ke = (tid & 1) * 16;
    const __nv_bfloat16* gA = A + (size_t)(m0 + lrow) * K2;
    const __nv_bfloat16* gB = Bt + (size_t)(n0 + lrow) * K2;
    const int a_ok = (m0 + lrow) < M ? 16 : 0;

    const int NIT = K / BKr;

    auto issue = [&](int it) {
        const int s = it % NSTG;
        const int k0 = it * BKr + ke;
        uint32_t d = sbase + s * STAGE_B;
        cp16(d + sw0,              gA + k0,         a_ok);
        cp16(d + sw1,              gA + k0 + 8,     a_ok);
        cp16(d + TILE_B + sw0,     gA + K + k0,     a_ok);
        cp16(d + TILE_B + sw1,     gA + K + k0 + 8, a_ok);
        cp16(d + 2 * TILE_B + sw0, gB + k0,         16);
        cp16(d + 2 * TILE_B + sw1, gB + k0 + 8,     16);
        cp16(d + 3 * TILE_B + sw0, gB + K + k0,     16);
        cp16(d + 3 * TILE_B + sw1, gB + K + k0 + 8, 16);
        cp_commit();
    };

    issue(0); issue(1);

    const int arow = wm * 32 + (lane & 15);
    const int acb = (lane >> 4) * 16;
    const int brow = wn * 64 + (lane & 7) + ((lane >> 4) << 3);
    const int bcb = ((lane >> 3) & 1) * 16;

    for (int it = 0; it < NIT; it++) {
        const int s = it % NSTG;
        cp_wait<NSTG - 2>();
        __syncthreads();
        if (it + 2 < NIT) issue(it + 2); else cp_commit();

        const uint32_t base = sbase + s * STAGE_B;
#pragma unroll
        for (int k16 = 0; k16 < 2; k16++) {
            const int kc = acb + k16 * 32;
            uint32_t ah[2][4], al[2][4];
#pragma unroll
            for (int mf = 0; mf < 2; mf++) {
                ldm4(ah[mf], base + swz(arow + mf * 16, kc));
                ldm4(al[mf], base + TILE_B + swz(arow + mf * 16, kc));
            }
            const int kb = bcb + k16 * 32;
#pragma unroll
            for (int ng = 0; ng < 4; ng++) {
                uint32_t bh[4], bl[4];
                ldm4(bh, base + 2 * TILE_B + swz(brow + ng * 16, kb));
                ldm4(bl, base + 3 * TILE_B + swz(brow + ng * 16, kb));
#pragma unroll
                for (int mf = 0; mf < 2; mf++) {
#pragma unroll
                    for (int t = 0; t < 2; t++) {
                        float* c = acc[mf][ng * 2 + t];
                        mma16816(c, ah[mf], bh + 2 * t);
                        mma16816(c, ah[mf], bl + 2 * t);
                        mma16816(c, al[mf], bh + 2 * t);
                    }
                }
            }
        }
    }

    // ---- epilogue: fp16 store + fused alpha partials ----
    float pS[2][2] = {{0.f, 0.f}, {0.f, 0.f}};   // [mf][rowA/rowB]
    float pD[2][2] = {{0.f, 0.f}, {0.f, 0.f}};
#pragma unroll
    for (int nf = 0; nf < 8; nf++) {
        const int n = n0 + wn * 64 + nf * 8 + (lane & 3) * 2;
        const float as0 = attS[n], as1 = attS[n + 1];
        const float ad0 = attD[n], ad1 = attD[n + 1];
#pragma unroll
        for (int mf = 0; mf < 2; mf++) {
            const float* c = acc[mf][nf];
            pS[mf][0] += c[0] * as0 + c[1] * as1;
            pS[mf][1] += c[2] * as0 + c[3] * as1;
            pD[mf][0] += c[0] * ad0 + c[1] * ad1;
            pD[mf][1] += c[2] * ad0 + c[3] * ad1;
        }
    }
#pragma unroll
    for (int o = 1; o <= 2; o <<= 1) {
#pragma unroll
        for (int mf = 0; mf < 2; mf++) {
#pragma unroll
            for (int r = 0; r < 2; r++) {
                pS[mf][r] += __shfl_xor_sync(0xffffffffu, pS[mf][r], o);
                pD[mf][r] += __shfl_xor_sync(0xffffffffu, pD[mf][r], o);
            }
        }
    }
    const int pidx = blockIdx.x * 2 + wn;
    if ((lane & 3) == 0) {
#pragma unroll
        for (int mf = 0; mf < 2; mf++) {
            const int rowA = m0 + wm * 32 + mf * 16 + (lane >> 2);
            const int rowB = rowA + 8;
            if (rowA < M) { pAS[pidx * NT + rowA] = pS[mf][0]; pAD[pidx * NT + rowA] = pD[mf][0]; }
            if (rowB < M) { pAS[pidx * NT + rowB] = pS[mf][1]; pAD[pidx * NT + rowB] = pD[mf][1]; }
        }
    }
#pragma unroll
    for (int mf = 0; mf < 2; mf++) {
        const int mA = m0 + wm * 32 + mf * 16 + (lane >> 2);
        const int mB = mA + 8;
#pragma unroll
        for (int nf = 0; nf < 8; nf++) {
            const int n = n0 + wn * 64 + nf * 8 + (lane & 3) * 2;
            const float* c = acc[mf][nf];
            if (mA < M) *(__half2*)(Ch + (size_t)mA * N + n) = __floats2half2_rn(c[0], c[1]);
            if (mB < M) *(__half2*)(Ch + (size_t)mB * N + n) = __floats2half2_rn(c[2], c[3]);
        }
    }
}

// ---------------- alpha partial reductions ----------------
__global__ void alpha_red1_kernel() {
    int i = blockIdx.x * blockDim.x + threadIdx.x;
    if (i >= NT) return;
    float s0 = 0.f, s1 = 0.f, d0 = 0.f, d1 = 0.f;
#pragma unroll
    for (int p = 0; p < 4; p++) { s0 += g_pas[p * NT + i]; d0 += g_pad[p * NT + i]; }
#pragma unroll
    for (int p = 4; p < 8; p++) { s1 += g_pas[p * NT + i]; d1 += g_pad[p * NT + i]; }
    g_as1[i * 2] = s0;     g_ad1[i * 2] = d0;
    g_as1[i * 2 + 1] = s1; g_ad1[i * 2 + 1] = d1;
}

__global__ void alpha_red2_kernel() {
    int i = blockIdx.x * blockDim.x + threadIdx.x;
    if (i >= NT) return;
    float s = 0.f, d = 0.f;
#pragma unroll
    for (int p = 0; p < 4; p++) { s += g_pas[p * NT + i]; d += g_pad[p * NT + i]; }
    g_as2[i] = s; g_ad2[i] = d;
}

// ---------------- conversion kernels ----------------
__global__ void conv_x_kernel(const float* __restrict__ x) {
    int i = blockIdx.x * blockDim.x + threadIdx.x;
    if (i >= NT * 128) return;
    int row = i >> 7;
    int c2 = (i & 127) << 1;
    float2 f = *(const float2*)(x + (size_t)row * FIN + c2);
    __nv_bfloat16 h0, l0, h1, l1;
    split_bf16(f.x, h0, l0);
    split_bf16(f.y, h1, l1);
    __nv_bfloat162 hp; hp.x = h0; hp.y = h1;
    __nv_bfloat162 lp; lp.x = l0; lp.y = l1;
    *(__nv_bfloat162*)(g_A1 + (size_t)row * 512 + c2) = hp;
    *(__nv_bfloat162*)(g_A1 + (size_t)row * 512 + 256 + c2) = lp;
}

__global__ void conv_w1_kernel(const float* __restrict__ W1) {
    int i = blockIdx.x * blockDim.x + threadIdx.x;   // over 512*512
    if (i >= 512 * 512) return;
    int n = i >> 9, k = i & 511;
    int ks = k & 255;
    float f = W1[(size_t)ks * F1 + n];
    __nv_bfloat16 hi, lo;
    split_bf16(f, hi, lo);
    g_Wt1[i] = (k < 256) ? hi : lo;
}

__global__ void conv_w2_kernel(const float* __restrict__ W2) {
    int i = blockIdx.x * blockDim.x + threadIdx.x;   // over 256*1024
    if (i >= 256 * 1024) return;
    int n = i >> 10, k = i & 1023;
    int ks = k & 511;
    float f = W2[(size_t)ks * FOUT + n];
    __nv_bfloat16 hi, lo;
    split_bf16(f, hi, lo);
    g_Wt2[i] = (k < 512) ? hi : lo;
}

// ---------------- edge enumeration ----------------
__device__ __forceinline__ void edge_sd(int j, const int* ei, int& s, int& d) {
    if (j < EB) {
        int b = j / EE;
        int k = j - b * EE;
        s = ei[k]      + b * NN;
        d = ei[EE + k] + b * NN;
    } else {
        s = d = j - EB;
    }
}

// ---------------- CSR build (forked stream) ----------------
__global__ void zero_cnt_kernel() {
    int i = blockIdx.x * blockDim.x + threadIdx.x;
    if (i <= NT) g_cnt[i] = 0;
}

__global__ void count_kernel(const int* __restrict__ ei) {
    int j = blockIdx.x * blockDim.x + threadIdx.x;
    if (j >= ET) return;
    int s, d;
    edge_sd(j, ei, s, d);
    atomicAdd(&g_cnt[d], 1);
}

__global__ void scan_kernel() {
    __shared__ int warp_base[32];
    int t = threadIdx.x;                 // 1024 threads
    int lane = t & 31, w = t >> 5;
    const int CH = 20;
    int base = t * CH;
    int local[CH];
    int sum = 0;
#pragma unroll
    for (int i = 0; i < CH; i++) {
        int idx = base + i;
        int v = (idx < NT) ? g_cnt[idx] : 0;
        local[i] = v;
        sum += v;
    }
    int inc = sum;
#pragma unroll
    for (int o = 1; o < 32; o <<= 1) {
        int v = __shfl_up_sync(0xffffffffu, inc, o);
        if (lane >= o) inc += v;
    }
    if (lane == 31) warp_base[w] = inc;
    __syncthreads();
    if (t < 32) {
        int v = warp_base[t];
        int wi = v;
#pragma unroll
        for (int o = 1; o < 32; o <<= 1) {
            int u = __shfl_up_sync(0xffffffffu, wi, o);
            if (t >= o) wi += u;
        }
        warp_base[t] = wi - v;
    }
    __syncthreads();
    int run = warp_base[w] + inc - sum;
#pragma unroll
    for (int i = 0; i < CH; i++) {
        int idx = base + i;
        if (idx < NT) { g_off[idx] = run; run += local[i]; }
    }
    if (t == 0) g_off[NT] = ET;
    for (int i = t; i < NT + 1; i += 1024) g_cnt[i] = 0;
}

__global__ void fill_kernel(const int* __restrict__ ei) {
    int j = blockIdx.x * blockDim.x + threadIdx.x;
    if (j >= ET) return;
    int s, d;
    edge_sd(j, ei, s, d);
    int pos = atomicAdd(&g_cnt[d], 1);
    g_srcidx[g_off[d] + pos] = s;
}

// ---------------- layer-1 aggregation: warp per (dst, head), fp16 gather, 2x unroll ----------------
__global__ void agg1_kernel(const float* __restrict__ b1) {
    int w = (blockIdx.x * blockDim.x + threadIdx.x) >> 5;
    int lane = threadIdx.x & 31;
    if (w >= NT * HH) return;
    int d = w >> 1;
    int h = w & 1;
    int beg = g_off[d], end = g_off[d + 1];
    float adh = g_ad1[d * HH + h];

    float acc[8] = {0.f, 0.f, 0.f, 0.f, 0.f, 0.f, 0.f, 0.f};
    float denom = 0.f;
    int j = beg;
    for (; j + 1 < end; j += 2) {
        int s0 = g_srcidx[j];
        int s1 = g_srcidx[j + 1];
        float e0 = g_as1[s0 * HH + h] + adh;
        float e1 = g_as1[s1 * HH + h] + adh;
        uint4 r0 = *(const uint4*)(g_xh1 + (size_t)s0 * F1 + h * HID + lane * 8);
        uint4 r1 = *(const uint4*)(g_xh1 + (size_t)s1 * F1 + h * HID + lane * 8);
        e0 = e0 > 0.f ? e0 : NEG_SLOPE * e0;
        e1 = e1 > 0.f ? e1 : NEG_SLOPE * e1;
        float ex0 = __expf(e0);
        float ex1 = __expf(e1);
        denom += ex0 + ex1;
        float2 a0 = __half22float2(*(const __half2*)&r0.x);
        float2 a1 = __half22float2(*(const __half2*)&r0.y);
        float2 a2 = __half22float2(*(const __half2*)&r0.z);
        float2 a3 = __half22float2(*(const __half2*)&r0.w);
        float2 c0 = __half22float2(*(const __half2*)&r1.x);
        float2 c1 = __half22float2(*(const __half2*)&r1.y);
        float2 c2 = __half22float2(*(const __half2*)&r1.z);
        float2 c3 = __half22float2(*(const __half2*)&r1.w);
        acc[0] += ex0 * a0.x + ex1 * c0.x; acc[1] += ex0 * a0.y + ex1 * c0.y;
        acc[2] += ex0 * a1.x + ex1 * c1.x; acc[3] += ex0 * a1.y + ex1 * c1.y;
        acc[4] += ex0 * a2.x + ex1 * c2.x; acc[5] += ex0 * a2.y + ex1 * c2.y;
        acc[6] += ex0 * a3.x + ex1 * c3.x; acc[7] += ex0 * a3.y + ex1 * c3.y;
    }
    if (j < end) {
        int s0 = g_srcidx[j];
        float e0 = g_as1[s0 * HH + h] + adh;
        e0 = e0 > 0.f ? e0 : NEG_SLOPE * e0;
        float ex0 = __expf(e0);
        denom += ex0;
        uint4 r0 = *(const uint4*)(g_xh1 + (size_t)s0 * F1 + h * HID + lane * 8);
        float2 a0 = __half22float2(*(const __half2*)&r0.x);
        float2 a1 = __half22float2(*(const __half2*)&r0.y);
        float2 a2 = __half22float2(*(const __half2*)&r0.z);
        float2 a3 = __half22float2(*(const __half2*)&r0.w);
        acc[0] += ex0 * a0.x; acc[1] += ex0 * a0.y;
        acc[2] += ex0 * a1.x; acc[3] += ex0 * a1.y;
        acc[4] += ex0 * a2.x; acc[5] += ex0 * a2.y;
        acc[6] += ex0 * a3.x; acc[7] += ex0 * a3.y;
    }
    float inv = 1.f / (denom + 1e-16f);
    __nv_bfloat16* outp = g_A2 + (size_t)d * 1024 + h * HID;
#pragma unroll
    for (int k = 0; k < 8; k++) {
        int c = lane * 8 + k;
        float v = acc[k] * inv + b1[h * HID + c];
        v = 0.5f * v * (1.f + erff(v * 0.70710678118654752f));   // exact gelu
        __nv_bfloat16 hi, lo;
        split_bf16(v, hi, lo);
        outp[c] = hi;
        outp[512 + c] = lo;
    }
}

// ---------------- layer-2 aggregation: warp per dst, fp16 gather, 2x unroll ----------------
__global__ void agg2_kernel(const float* __restrict__ b2, float* __restrict__ out) {
    int d = (blockIdx.x * blockDim.x + threadIdx.x) >> 5;
    int lane = threadIdx.x & 31;
    if (d >= NT) return;
    int beg = g_off[d], end = g_off[d + 1];
    float adh = g_ad2[d];

    float acc[8] = {0.f, 0.f, 0.f, 0.f, 0.f, 0.f, 0.f, 0.f};
    float denom = 0.f;
    int j = beg;
    for (; j + 1 < end; j += 2) {
        int s0 = g_srcidx[j];
        int s1 = g_srcidx[j + 1];
        float e0 = g_as2[s0] + adh;
        float e1 = g_as2[s1] + adh;
        uint4 r0 = *(const uint4*)(g_xh2 + (size_t)s0 * FOUT + lane * 8);
        uint4 r1 = *(const uint4*)(g_xh2 + (size_t)s1 * FOUT + lane * 8);
        e0 = e0 > 0.f ? e0 : NEG_SLOPE * e0;
        e1 = e1 > 0.f ? e1 : NEG_SLOPE * e1;
        float ex0 = __expf(e0);
        float ex1 = __expf(e1);
        denom += ex0 + ex1;
        float2 a0 = __half22float2(*(const __half2*)&r0.x);
        float2 a1 = __half22float2(*(const __half2*)&r0.y);
        float2 a2 = __half22float2(*(const __half2*)&r0.z);
        float2 a3 = __half22float2(*(const __half2*)&r0.w);
        float2 c0 = __half22float2(*(const __half2*)&r1.x);
        float2 c1 = __half22float2(*(const __half2*)&r1.y);
        float2 c2 = __half22float2(*(const __half2*)&r1.z);
        float2 c3 = __half22float2(*(const __half2*)&r1.w);
        acc[0] += ex0 * a0.x + ex1 * c0.x; acc[1] += ex0 * a0.y + ex1 * c0.y;
        acc[2] += ex0 * a1.x + ex1 * c1.x; acc[3] += ex0 * a1.y + ex1 * c1.y;
        acc[4] += ex0 * a2.x + ex1 * c2.x; acc[5] += ex0 * a2.y + ex1 * c2.y;
        acc[6] += ex0 * a3.x + ex1 * c3.x; acc[7] += ex0 * a3.y + ex1 * c3.y;
    }
    if (j < end) {
        int s0 = g_srcidx[j];
        float e0 = g_as2[s0] + adh;
        e0 = e0 > 0.f ? e0 : NEG_SLOPE * e0;
        float ex0 = __expf(e0);
        denom += ex0;
        uint4 r0 = *(const uint4*)(g_xh2 + (size_t)s0 * FOUT + lane * 8);
        float2 a0 = __half22float2(*(const __half2*)&r0.x);
        float2 a1 = __half22float2(*(const __half2*)&r0.y);
        float2 a2 = __half22float2(*(const __half2*)&r0.z);
        float2 a3 = __half22float2(*(const __half2*)&r0.w);
        acc[0] += ex0 * a0.x; acc[1] += ex0 * a0.y;
        acc[2] += ex0 * a1.x; acc[3] += ex0 * a1.y;
        acc[4] += ex0 * a2.x; acc[5] += ex0 * a2.y;
        acc[6] += ex0 * a3.x; acc[7] += ex0 * a3.y;
    }
    float inv = 1.f / (denom + 1e-16f);
    float* outp = out + (size_t)d * FOUT + lane * 8;
    float4 o0 = make_float4(acc[0] * inv + b2[lane * 8 + 0],
                            acc[1] * inv + b2[lane * 8 + 1],
                            acc[2] * inv + b2[lane * 8 + 2],
                            acc[3] * inv + b2[lane * 8 + 3]);
    float4 o1 = make_float4(acc[4] * inv + b2[lane * 8 + 4],
                            acc[5] * inv + b2[lane * 8 + 5],
                            acc[6] * inv + b2[lane * 8 + 6],
                            acc[7] * inv + b2[lane * 8 + 7]);
    *(float4*)(outp) = o0;
    *(float4*)(outp + 4) = o1;
}

// ---------------- launch ----------------
extern "C" void kernel_launch(void* const* d_in, const int* in_sizes, int n_in,
                              void* d_out, int out_size) {
    const float* x        = (const float*)d_in[0];
    const int*   ei       = (const int*)  d_in[1];
    const float* W1       = (const float*)d_in[2];
    const float* att_src1 = (const float*)d_in[3];
    const float* att_dst1 = (const float*)d_in[4];
    const float* b1       = (const float*)d_in[5];
    const float* W2       = (const float*)d_in[6];
    const float* att_src2 = (const float*)d_in[7];
    const float* att_dst2 = (const float*)d_in[8];
    const float* b2       = (const float*)d_in[9];
    float* out = (float*)d_out;

    __half *p_xh1, *p_xh2;
    __nv_bfloat16 *p_A1, *p_A2, *p_Wt1, *p_Wt2;
    float *p_pas, *p_pad;
    cudaGetSymbolAddress((void**)&p_xh1, g_xh1);
    cudaGetSymbolAddress((void**)&p_xh2, g_xh2);
    cudaGetSymbolAddress((void**)&p_A1,  g_A1);
    cudaGetSymbolAddress((void**)&p_A2,  g_A2);
    cudaGetSymbolAddress((void**)&p_Wt1, g_Wt1);
    cudaGetSymbolAddress((void**)&p_Wt2, g_Wt2);
    cudaGetSymbolAddress((void**)&p_pas, g_pas);
    cudaGetSymbolAddress((void**)&p_pad, g_pad);

    static cudaStream_t s2 = nullptr;
    static cudaEvent_t evFork = nullptr, evJoin = nullptr;
    if (!s2) {
        cudaStreamCreateWithFlags(&s2, cudaStreamNonBlocking);
        cudaEventCreateWithFlags(&evFork, cudaEventDisableTiming);
        cudaEventCreateWithFlags(&evJoin, cudaEventDisableTiming);
        cudaFuncSetAttribute(gemm_kernel, cudaFuncAttributeMaxDynamicSharedMemorySize, GEMM_SMEM);
    }

    // ---- fork: CSR build + conv_w2 on s2 ----
    cudaEventRecord(evFork, 0);
    cudaStreamWaitEvent(s2, evFork, 0);
    zero_cnt_kernel<<<(NT + 256) / 256, 256, 0, s2>>>();
    count_kernel<<<(ET + 255) / 256, 256, 0, s2>>>(ei);
    scan_kernel<<<1, 1024, 0, s2>>>();
    fill_kernel<<<(ET + 255) / 256, 256, 0, s2>>>(ei);
    conv_w2_kernel<<<(256 * 1024 + 255) / 256, 256, 0, s2>>>(W2);
    cudaEventRecord(evJoin, s2);

    // ---- main: conversions + layer-1 GEMM (fused alphas) ----
    conv_x_kernel<<<(NT * 128 + 255) / 256, 256>>>(x);
    conv_w1_kernel<<<(512 * 512 + 255) / 256, 256>>>(W1);
    {
        dim3 grid(F1 / BN, (NT + BM - 1) / BM);
        gemm_kernel<<<grid, 256, GEMM_SMEM>>>(p_A1, p_Wt1, p_xh1,
                                              att_src1, att_dst1, p_pas, p_pad,
                                              NT, F1, 256);
    }
    alpha_red1_kernel<<<(NT + 255) / 256, 256>>>();

    // ---- join CSR, then aggregate ----
    cudaStreamWaitEvent(0, evJoin, 0);
    agg1_kernel<<<(NT * HH * 32 + 255) / 256, 256>>>(b1);

    // layer-2 GEMM (fused alphas)
    {
        dim3 grid(FOUT / BN, (NT + BM - 1) / BM);
        gemm_kernel<<<grid, 256, GEMM_SMEM>>>(p_A2, p_Wt2, p_xh2,
                                              att_src2, att_dst2, p_pas, p_pad,
                                              NT, FOUT, 512);
    }
    alpha_red2_kernel<<<(NT + 255) / 256, 256>>>();
    agg2_kernel<<<(NT * 32 + 255) / 256, 256>>>(b2, out);
}

// round 9
// speedup vs baseline: 1.3738x; 1.3738x over previous
#include <cuda_runtime.h>
#include <cuda_bf16.h>
#include <cuda_fp16.h>
#include <math.h>
#include <stdint.h>

// ---------------- problem constants ----------------
#define BB   2
#define NN   10000
#define NT   20000           // BB*NN nodes
#define EE   160000          // edges per graph
#define EB   320000          // BB*EE batched edges
#define ET   340000          // EB + NT self loops
#define FIN  256
#define HID  256
#define HH   2
#define F1   512             // HH*HID
#define FOUT 256
#define NEG_SLOPE 0.2f

// ---------------- device scratch ----------------
__device__ __half g_xh1[(size_t)NT * F1];            // fp16 xw1 (gathers + alphas)
__device__ __half g_xh2[(size_t)NT * FOUT];          // fp16 xw2 (gathers + alphas)
__device__ __nv_bfloat16 g_A1[(size_t)NT * 512];     // [x_hi(256) | x_lo(256)]
__device__ __nv_bfloat16 g_A2[(size_t)NT * 1024];    // [h_hi(512) | h_lo(512)]
__device__ __nv_bfloat16 g_Wt1[(size_t)512 * 512];   // W1^T: [n=512][hi(256)|lo(256)]
__device__ __nv_bfloat16 g_Wt2[(size_t)256 * 1024];  // W2^T: [n=256][hi(512)|lo(512)]
__device__ float g_as1[NT * HH];
__device__ float g_ad1[NT * HH];
__device__ float g_as2[NT];
__device__ float g_ad2[NT];
__device__ int   g_cnt[NT + 1];
__device__ int   g_off[NT + 1];
__device__ int   g_srcidx[ET];

// ---------------- helpers ----------------
__device__ __forceinline__ uint32_t smem_u32(const void* p) {
    return (uint32_t)__cvta_generic_to_shared(p);
}
__device__ __forceinline__ void cp16(uint32_t dst, const void* src, int src_sz) {
    asm volatile("cp.async.cg.shared.global [%0], [%1], 16, %2;"
                 :: "r"(dst), "l"(src), "r"(src_sz) : "memory");
}
__device__ __forceinline__ void cp_commit() {
    asm volatile("cp.async.commit_group;" ::: "memory");
}
template <int N>
__device__ __forceinline__ void cp_wait() {
    asm volatile("cp.async.wait_group %0;" :: "n"(N) : "memory");
}
__device__ __forceinline__ void ldm4(uint32_t* r, uint32_t addr) {
    asm volatile("ldmatrix.sync.aligned.m8n8.x4.shared.b16 {%0,%1,%2,%3}, [%4];"
                 : "=r"(r[0]), "=r"(r[1]), "=r"(r[2]), "=r"(r[3]) : "r"(addr));
}
__device__ __forceinline__ void mma16816(float* c, const uint32_t* a, const uint32_t* b) {
    asm volatile(
        "mma.sync.aligned.m16n8k16.row.col.f32.bf16.bf16.f32 "
        "{%0,%1,%2,%3}, {%4,%5,%6,%7}, {%8,%9}, {%0,%1,%2,%3};"
        : "+f"(c[0]), "+f"(c[1]), "+f"(c[2]), "+f"(c[3])
        : "r"(a[0]), "r"(a[1]), "r"(a[2]), "r"(a[3]), "r"(b[0]), "r"(b[1]));
}
__device__ __forceinline__ void split_bf16(float f, __nv_bfloat16& hi, __nv_bfloat16& lo) {
    hi = __float2bfloat16(f);
    lo = __float2bfloat16(f - __bfloat162float(hi));
}
// XOR swizzle: 64B rows, chunk' = chunk ^ ((row>>1)&3); conflict-free ldmatrix, 16B-aligned
__device__ __forceinline__ uint32_t swz(int row, int cByte) {
    return (uint32_t)(row * 64 + (cByte ^ ((((row >> 1) & 3)) << 4)));
}

// ---------------- bf16x3 mma.sync GEMM, 3-stage cp.async, BKr=32 ----------------
// C = A @ Bt^T -> fp16 output only.
#define BM 128
#define BN 128
#define BKr 32
#define TILE_B (128 * 64)            // 8192 bytes per tile (swizzled, no pad)
#define STAGE_B (4 * TILE_B)         // Ah, Al, Bh, Bl = 32768
#define NSTG 3
#define GEMM_SMEM (NSTG * STAGE_B)   // 98304 bytes

__global__ __launch_bounds__(256, 2)
void gemm_kernel(const __nv_bfloat16* __restrict__ A,
                 const __nv_bfloat16* __restrict__ Bt,
                 __half* __restrict__ Ch, int M, int N, int K) {
    extern __shared__ char sm[];
    const int tid = threadIdx.x;
    const int lane = tid & 31;
    const int wid = tid >> 5;
    const int wm = wid & 3;          // 4 warps over M (32 rows each)
    const int wn = wid >> 2;         // 2 warps over N (64 cols each)
    const int m0 = blockIdx.y * BM;
    const int n0 = blockIdx.x * BN;
    const int K2 = 2 * K;
    const uint32_t sbase = smem_u32(sm);

    float acc[2][8][4];
#pragma unroll
    for (int i = 0; i < 2; i++)
#pragma unroll
        for (int j = 0; j < 8; j++)
#pragma unroll
            for (int t = 0; t < 4; t++) acc[i][j][t] = 0.f;

    // loader
    const int lrow = tid >> 1;
    const int cb = (tid & 1) * 32;
    const uint32_t sw0 = swz(lrow, cb);
    const uint32_t sw1 = swz(lrow, cb + 16);
    const int ke = (tid & 1) * 16;
    const __nv_bfloat16* gA = A + (size_t)(m0 + lrow) * K2;
    const __nv_bfloat16* gB = Bt + (size_t)(n0 + lrow) * K2;
    const int a_ok = (m0 + lrow) < M ? 16 : 0;

    const int NIT = K / BKr;

    auto issue = [&](int it) {
        const int s = it % NSTG;
        const int k0 = it * BKr + ke;
        uint32_t d = sbase + s * STAGE_B;
        cp16(d + sw0,              gA + k0,         a_ok);
        cp16(d + sw1,              gA + k0 + 8,     a_ok);
        cp16(d + TILE_B + sw0,     gA + K + k0,     a_ok);
        cp16(d + TILE_B + sw1,     gA + K + k0 + 8, a_ok);
        cp16(d + 2 * TILE_B + sw0, gB + k0,         16);
        cp16(d + 2 * TILE_B + sw1, gB + k0 + 8,     16);
        cp16(d + 3 * TILE_B + sw0, gB + K + k0,     16);
        cp16(d + 3 * TILE_B + sw1, gB + K + k0 + 8, 16);
        cp_commit();
    };

    issue(0); issue(1);

    const int arow = wm * 32 + (lane & 15);
    const int acb = (lane >> 4) * 16;
    const int brow = wn * 64 + (lane & 7) + ((lane >> 4) << 3);
    const int bcb = ((lane >> 3) & 1) * 16;

    for (int it = 0; it < NIT; it++) {
        const int s = it % NSTG;
        cp_wait<NSTG - 2>();
        __syncthreads();
        if (it + 2 < NIT) issue(it + 2); else cp_commit();

        const uint32_t base = sbase + s * STAGE_B;
#pragma unroll
        for (int k16 = 0; k16 < 2; k16++) {
            const int kc = acb + k16 * 32;
            uint32_t ah[2][4], al[2][4];
#pragma unroll
            for (int mf = 0; mf < 2; mf++) {
                ldm4(ah[mf], base + swz(arow + mf * 16, kc));
                ldm4(al[mf], base + TILE_B + swz(arow + mf * 16, kc));
            }
            const int kb = bcb + k16 * 32;
#pragma unroll
            for (int ng = 0; ng < 4; ng++) {
                uint32_t bh[4], bl[4];
                ldm4(bh, base + 2 * TILE_B + swz(brow + ng * 16, kb));
                ldm4(bl, base + 3 * TILE_B + swz(brow + ng * 16, kb));
#pragma unroll
                for (int mf = 0; mf < 2; mf++) {
#pragma unroll
                    for (int t = 0; t < 2; t++) {
                        float* c = acc[mf][ng * 2 + t];
                        mma16816(c, ah[mf], bh + 2 * t);
                        mma16816(c, ah[mf], bl + 2 * t);
                        mma16816(c, al[mf], bh + 2 * t);
                    }
                }
            }
        }
    }

    // epilogue: fp16 store only
#pragma unroll
    for (int mf = 0; mf < 2; mf++) {
        const int mA = m0 + wm * 32 + mf * 16 + (lane >> 2);
        const int mB = mA + 8;
#pragma unroll
        for (int nf = 0; nf < 8; nf++) {
            const int n = n0 + wn * 64 + nf * 8 + (lane & 3) * 2;
            const float* c = acc[mf][nf];
            if (mA < M) *(__half2*)(Ch + (size_t)mA * N + n) = __floats2half2_rn(c[0], c[1]);
            if (mB < M) *(__half2*)(Ch + (size_t)mB * N + n) = __floats2half2_rn(c[2], c[3]);
        }
    }
}

// ---------------- conversion kernels ----------------
__global__ void conv_x_kernel(const float* __restrict__ x) {
    int i = blockIdx.x * blockDim.x + threadIdx.x;
    if (i >= NT * 128) return;
    int row = i >> 7;
    int c2 = (i & 127) << 1;
    float2 f = *(const float2*)(x + (size_t)row * FIN + c2);
    __nv_bfloat16 h0, l0, h1, l1;
    split_bf16(f.x, h0, l0);
    split_bf16(f.y, h1, l1);
    __nv_bfloat162 hp; hp.x = h0; hp.y = h1;
    __nv_bfloat162 lp; lp.x = l0; lp.y = l1;
    *(__nv_bfloat162*)(g_A1 + (size_t)row * 512 + c2) = hp;
    *(__nv_bfloat162*)(g_A1 + (size_t)row * 512 + 256 + c2) = lp;
}

__global__ void conv_w1_kernel(const float* __restrict__ W1) {
    int i = blockIdx.x * blockDim.x + threadIdx.x;   // over 512*512
    if (i >= 512 * 512) return;
    int n = i >> 9, k = i & 511;
    int ks = k & 255;
    float f = W1[(size_t)ks * F1 + n];
    __nv_bfloat16 hi, lo;
    split_bf16(f, hi, lo);
    g_Wt1[i] = (k < 256) ? hi : lo;
}

__global__ void conv_w2_kernel(const float* __restrict__ W2) {
    int i = blockIdx.x * blockDim.x + threadIdx.x;   // over 256*1024
    if (i >= 256 * 1024) return;
    int n = i >> 10, k = i & 1023;
    int ks = k & 511;
    float f = W2[(size_t)ks * FOUT + n];
    __nv_bfloat16 hi, lo;
    split_bf16(f, hi, lo);
    g_Wt2[i] = (k < 512) ? hi : lo;
}

// ---------------- edge enumeration ----------------
__device__ __forceinline__ void edge_sd(int j, const int* ei, int& s, int& d) {
    if (j < EB) {
        int b = j / EE;
        int k = j - b * EE;
        s = ei[k]      + b * NN;
        d = ei[EE + k] + b * NN;
    } else {
        s = d = j - EB;
    }
}

// ---------------- alphas: warp per node, fp16 reads ----------------
__global__ void alpha1_kernel(const float* __restrict__ att_src,
                              const float* __restrict__ att_dst) {
    int gid = blockIdx.x * blockDim.x + threadIdx.x;
    int w = gid >> 5;
    int lane = gid & 31;
    if (w >= NT) return;
#pragma unroll
    for (int h = 0; h < HH; h++) {
        uint4 r = *(const uint4*)(g_xh1 + (size_t)w * F1 + h * HID + lane * 8);
        float2 v0 = __half22float2(*(const __half2*)&r.x);
        float2 v1 = __half22float2(*(const __half2*)&r.y);
        float2 v2 = __half22float2(*(const __half2*)&r.z);
        float2 v3 = __half22float2(*(const __half2*)&r.w);
        const float* as = att_src + h * HID + lane * 8;
        const float* ad = att_dst + h * HID + lane * 8;
        float4 s0 = *(const float4*)(as);
        float4 s1 = *(const float4*)(as + 4);
        float4 d0 = *(const float4*)(ad);
        float4 d1 = *(const float4*)(ad + 4);
        float ps = v0.x * s0.x + v0.y * s0.y + v1.x * s0.z + v1.y * s0.w
                 + v2.x * s1.x + v2.y * s1.y + v3.x * s1.z + v3.y * s1.w;
        float pd = v0.x * d0.x + v0.y * d0.y + v1.x * d0.z + v1.y * d0.w
                 + v2.x * d1.x + v2.y * d1.y + v3.x * d1.z + v3.y * d1.w;
#pragma unroll
        for (int o = 16; o > 0; o >>= 1) {
            ps += __shfl_xor_sync(0xffffffffu, ps, o);
            pd += __shfl_xor_sync(0xffffffffu, pd, o);
        }
        if (lane == 0) { g_as1[w * HH + h] = ps; g_ad1[w * HH + h] = pd; }
    }
}

__global__ void alpha2_kernel(const float* __restrict__ att_src,
                              const float* __restrict__ att_dst) {
    int gid = blockIdx.x * blockDim.x + threadIdx.x;
    int w = gid >> 5;
    int lane = gid & 31;
    if (w >= NT) return;
    uint4 r = *(const uint4*)(g_xh2 + (size_t)w * FOUT + lane * 8);
    float2 v0 = __half22float2(*(const __half2*)&r.x);
    float2 v1 = __half22float2(*(const __half2*)&r.y);
    float2 v2 = __half22float2(*(const __half2*)&r.z);
    float2 v3 = __half22float2(*(const __half2*)&r.w);
    const float* as = att_src + lane * 8;
    const float* ad = att_dst + lane * 8;
    float4 s0 = *(const float4*)(as);
    float4 s1 = *(const float4*)(as + 4);
    float4 d0 = *(const float4*)(ad);
    float4 d1 = *(const float4*)(ad + 4);
    float ps = v0.x * s0.x + v0.y * s0.y + v1.x * s0.z + v1.y * s0.w
             + v2.x * s1.x + v2.y * s1.y + v3.x * s1.z + v3.y * s1.w;
    float pd = v0.x * d0.x + v0.y * d0.y + v1.x * d0.z + v1.y * d0.w
             + v2.x * d1.x + v2.y * d1.y + v3.x * d1.z + v3.y * d1.w;
#pragma unroll
    for (int o = 16; o > 0; o >>= 1) {
        ps += __shfl_xor_sync(0xffffffffu, ps, o);
        pd += __shfl_xor_sync(0xffffffffu, pd, o);
    }
    if (lane == 0) { g_as2[w] = ps; g_ad2[w] = pd; }
}

// ---------------- CSR build (forked stream) ----------------
__global__ void zero_cnt_kernel() {
    int i = blockIdx.x * blockDim.x + threadIdx.x;
    if (i <= NT) g_cnt[i] = 0;
}

__global__ void count_kernel(const int* __restrict__ ei) {
    int j = blockIdx.x * blockDim.x + threadIdx.x;
    if (j >= ET) return;
    int s, d;
    edge_sd(j, ei, s, d);
    atomicAdd(&g_cnt[d], 1);
}

__global__ void scan_kernel() {
    __shared__ int warp_base[32];
    int t = threadIdx.x;                 // 1024 threads
    int lane = t & 31, w = t >> 5;
    const int CH = 20;
    int base = t * CH;
    int local[CH];
    int sum = 0;
#pragma unroll
    for (int i = 0; i < CH; i++) {
        int idx = base + i;
        int v = (idx < NT) ? g_cnt[idx] : 0;
        local[i] = v;
        sum += v;
    }
    int inc = sum;
#pragma unroll
    for (int o = 1; o < 32; o <<= 1) {
        int v = __shfl_up_sync(0xffffffffu, inc, o);
        if (lane >= o) inc += v;
    }
    if (lane == 31) warp_base[w] = inc;
    __syncthreads();
    if (t < 32) {
        int v = warp_base[t];
        int wi = v;
#pragma unroll
        for (int o = 1; o < 32; o <<= 1) {
            int u = __shfl_up_sync(0xffffffffu, wi, o);
            if (t >= o) wi += u;
        }
        warp_base[t] = wi - v;
    }
    __syncthreads();
    int run = warp_base[w] + inc - sum;
#pragma unroll
    for (int i = 0; i < CH; i++) {
        int idx = base + i;
        if (idx < NT) { g_off[idx] = run; run += local[i]; }
    }
    if (t == 0) g_off[NT] = ET;
    for (int i = t; i < NT + 1; i += 1024) g_cnt[i] = 0;
}

__global__ void fill_kernel(const int* __restrict__ ei) {
    int j = blockIdx.x * blockDim.x + threadIdx.x;
    if (j >= ET) return;
    int s, d;
    edge_sd(j, ei, s, d);
    int pos = atomicAdd(&g_cnt[d], 1);
    g_srcidx[g_off[d] + pos] = s;
}

// ---------------- layer-1 aggregation: warp per (dst, head), fp16 gather, 2x unroll ----------------
__global__ void agg1_kernel(const float* __restrict__ b1) {
    int w = (blockIdx.x * blockDim.x + threadIdx.x) >> 5;
    int lane = threadIdx.x & 31;
    if (w >= NT * HH) return;
    int d = w >> 1;
    int h = w & 1;
    int beg = g_off[d], end = g_off[d + 1];
    float adh = g_ad1[d * HH + h];

    float acc[8] = {0.f, 0.f, 0.f, 0.f, 0.f, 0.f, 0.f, 0.f};
    float denom = 0.f;
    int j = beg;
    for (; j + 1 < end; j += 2) {
        int s0 = g_srcidx[j];
        int s1 = g_srcidx[j + 1];
        float e0 = g_as1[s0 * HH + h] + adh;
        float e1 = g_as1[s1 * HH + h] + adh;
        uint4 r0 = *(const uint4*)(g_xh1 + (size_t)s0 * F1 + h * HID + lane * 8);
        uint4 r1 = *(const uint4*)(g_xh1 + (size_t)s1 * F1 + h * HID + lane * 8);
        e0 = e0 > 0.f ? e0 : NEG_SLOPE * e0;
        e1 = e1 > 0.f ? e1 : NEG_SLOPE * e1;
        float ex0 = __expf(e0);
        float ex1 = __expf(e1);
        denom += ex0 + ex1;
        float2 a0 = __half22float2(*(const __half2*)&r0.x);
        float2 a1 = __half22float2(*(const __half2*)&r0.y);
        float2 a2 = __half22float2(*(const __half2*)&r0.z);
        float2 a3 = __half22float2(*(const __half2*)&r0.w);
        float2 c0 = __half22float2(*(const __half2*)&r1.x);
        float2 c1 = __half22float2(*(const __half2*)&r1.y);
        float2 c2 = __half22float2(*(const __half2*)&r1.z);
        float2 c3 = __half22float2(*(const __half2*)&r1.w);
        acc[0] += ex0 * a0.x + ex1 * c0.x; acc[1] += ex0 * a0.y + ex1 * c0.y;
        acc[2] += ex0 * a1.x + ex1 * c1.x; acc[3] += ex0 * a1.y + ex1 * c1.y;
        acc[4] += ex0 * a2.x + ex1 * c2.x; acc[5] += ex0 * a2.y + ex1 * c2.y;
        acc[6] += ex0 * a3.x + ex1 * c3.x; acc[7] += ex0 * a3.y + ex1 * c3.y;
    }
    if (j < end) {
        int s0 = g_srcidx[j];
        float e0 = g_as1[s0 * HH + h] + adh;
        e0 = e0 > 0.f ? e0 : NEG_SLOPE * e0;
        float ex0 = __expf(e0);
        denom += ex0;
        uint4 r0 = *(const uint4*)(g_xh1 + (size_t)s0 * F1 + h * HID + lane * 8);
        float2 a0 = __half22float2(*(const __half2*)&r0.x);
        float2 a1 = __half22float2(*(const __half2*)&r0.y);
        float2 a2 = __half22float2(*(const __half2*)&r0.z);
        float2 a3 = __half22float2(*(const __half2*)&r0.w);
        acc[0] += ex0 * a0.x; acc[1] += ex0 * a0.y;
        acc[2] += ex0 * a1.x; acc[3] += ex0 * a1.y;
        acc[4] += ex0 * a2.x; acc[5] += ex0 * a2.y;
        acc[6] += ex0 * a3.x; acc[7] += ex0 * a3.y;
    }
    float inv = 1.f / (denom + 1e-16f);
    __nv_bfloat16* outp = g_A2 + (size_t)d * 1024 + h * HID;
#pragma unroll
    for (int k = 0; k < 8; k++) {
        int c = lane * 8 + k;
        float v = acc[k] * inv + b1[h * HID + c];
        v = 0.5f * v * (1.f + erff(v * 0.70710678118654752f));   // exact gelu
        __nv_bfloat16 hi, lo;
        split_bf16(v, hi, lo);
        outp[c] = hi;
        outp[512 + c] = lo;
    }
}

// ---------------- layer-2 aggregation: warp per dst, fp16 gather, 2x unroll ----------------
__global__ void agg2_kernel(const float* __restrict__ b2, float* __restrict__ out) {
    int d = (blockIdx.x * blockDim.x + threadIdx.x) >> 5;
    int lane = threadIdx.x & 31;
    if (d >= NT) return;
    int beg = g_off[d], end = g_off[d + 1];
    float adh = g_ad2[d];

    float acc[8] = {0.f, 0.f, 0.f, 0.f, 0.f, 0.f, 0.f, 0.f};
    float denom = 0.f;
    int j = beg;
    for (; j + 1 < end; j += 2) {
        int s0 = g_srcidx[j];
        int s1 = g_srcidx[j + 1];
        float e0 = g_as2[s0] + adh;
        float e1 = g_as2[s1] + adh;
        uint4 r0 = *(const uint4*)(g_xh2 + (size_t)s0 * FOUT + lane * 8);
        uint4 r1 = *(const uint4*)(g_xh2 + (size_t)s1 * FOUT + lane * 8);
        e0 = e0 > 0.f ? e0 : NEG_SLOPE * e0;
        e1 = e1 > 0.f ? e1 : NEG_SLOPE * e1;
        float ex0 = __expf(e0);
        float ex1 = __expf(e1);
        denom += ex0 + ex1;
        float2 a0 = __half22float2(*(const __half2*)&r0.x);
        float2 a1 = __half22float2(*(const __half2*)&r0.y);
        float2 a2 = __half22float2(*(const __half2*)&r0.z);
        float2 a3 = __half22float2(*(const __half2*)&r0.w);
        float2 c0 = __half22float2(*(const __half2*)&r1.x);
        float2 c1 = __half22float2(*(const __half2*)&r1.y);
        float2 c2 = __half22float2(*(const __half2*)&r1.z);
        float2 c3 = __half22float2(*(const __half2*)&r1.w);
        acc[0] += ex0 * a0.x + ex1 * c0.x; acc[1] += ex0 * a0.y + ex1 * c0.y;
        acc[2] += ex0 * a1.x + ex1 * c1.x; acc[3] += ex0 * a1.y + ex1 * c1.y;
        acc[4] += ex0 * a2.x + ex1 * c2.x; acc[5] += ex0 * a2.y + ex1 * c2.y;
        acc[6] += ex0 * a3.x + ex1 * c3.x; acc[7] += ex0 * a3.y + ex1 * c3.y;
    }
    if (j < end) {
        int s0 = g_srcidx[j];
        float e0 = g_as2[s0] + adh;
        e0 = e0 > 0.f ? e0 : NEG_SLOPE * e0;
        float ex0 = __expf(e0);
        denom += ex0;
        uint4 r0 = *(const uint4*)(g_xh2 + (size_t)s0 * FOUT + lane * 8);
        float2 a0 = __half22float2(*(const __half2*)&r0.x);
        float2 a1 = __half22float2(*(const __half2*)&r0.y);
        float2 a2 = __half22float2(*(const __half2*)&r0.z);
        float2 a3 = __half22float2(*(const __half2*)&r0.w);
        acc[0] += ex0 * a0.x; acc[1] += ex0 * a0.y;
        acc[2] += ex0 * a1.x; acc[3] += ex0 * a1.y;
        acc[4] += ex0 * a2.x; acc[5] += ex0 * a2.y;
        acc[6] += ex0 * a3.x; acc[7] += ex0 * a3.y;
    }
    float inv = 1.f / (denom + 1e-16f);
    float* outp = out + (size_t)d * FOUT + lane * 8;
    float4 o0 = make_float4(acc[0] * inv + b2[lane * 8 + 0],
                            acc[1] * inv + b2[lane * 8 + 1],
                            acc[2] * inv + b2[lane * 8 + 2],
                            acc[3] * inv + b2[lane * 8 + 3]);
    float4 o1 = make_float4(acc[4] * inv + b2[lane * 8 + 4],
                            acc[5] * inv + b2[lane * 8 + 5],
                            acc[6] * inv + b2[lane * 8 + 6],
                            acc[7] * inv + b2[lane * 8 + 7]);
    *(float4*)(outp) = o0;
    *(float4*)(outp + 4) = o1;
}

// ---------------- launch ----------------
extern "C" void kernel_launch(void* const* d_in, const int* in_sizes, int n_in,
                              void* d_out, int out_size) {
    const float* x        = (const float*)d_in[0];
    const int*   ei       = (const int*)  d_in[1];
    const float* W1       = (const float*)d_in[2];
    const float* att_src1 = (const float*)d_in[3];
    const float* att_dst1 = (const float*)d_in[4];
    const float* b1       = (const float*)d_in[5];
    const float* W2       = (const float*)d_in[6];
    const float* att_src2 = (const float*)d_in[7];
    const float* att_dst2 = (const float*)d_in[8];
    const float* b2       = (const float*)d_in[9];
    float* out = (float*)d_out;

    __half *p_xh1, *p_xh2;
    __nv_bfloat16 *p_A1, *p_A2, *p_Wt1, *p_Wt2;
    cudaGetSymbolAddress((void**)&p_xh1, g_xh1);
    cudaGetSymbolAddress((void**)&p_xh2, g_xh2);
    cudaGetSymbolAddress((void**)&p_A1,  g_A1);
    cudaGetSymbolAddress((void**)&p_A2,  g_A2);
    cudaGetSymbolAddress((void**)&p_Wt1, g_Wt1);
    cudaGetSymbolAddress((void**)&p_Wt2, g_Wt2);

    static cudaStream_t s2 = nullptr;
    static cudaEvent_t evFork = nullptr, evJoin = nullptr;
    if (!s2) {
        cudaStreamCreateWithFlags(&s2, cudaStreamNonBlocking);
        cudaEventCreateWithFlags(&evFork, cudaEventDisableTiming);
        cudaEventCreateWithFlags(&evJoin, cudaEventDisableTiming);
        cudaFuncSetAttribute(gemm_kernel, cudaFuncAttributeMaxDynamicSharedMemorySize, GEMM_SMEM);
    }

    // ---- fork: CSR build + conv_w2 on s2 ----
    cudaEventRecord(evFork, 0);
    cudaStreamWaitEvent(s2, evFork, 0);
    zero_cnt_kernel<<<(NT + 256) / 256, 256, 0, s2>>>();
    count_kernel<<<(ET + 255) / 256, 256, 0, s2>>>(ei);
    scan_kernel<<<1, 1024, 0, s2>>>();
    fill_kernel<<<(ET + 255) / 256, 256, 0, s2>>>(ei);
    conv_w2_kernel<<<(256 * 1024 + 255) / 256, 256, 0, s2>>>(W2);
    cudaEventRecord(evJoin, s2);

    // ---- main: conversions + layer-1 GEMM + alpha1 ----
    conv_x_kernel<<<(NT * 128 + 255) / 256, 256>>>(x);
    conv_w1_kernel<<<(512 * 512 + 255) / 256, 256>>>(W1);
    {
        dim3 grid(F1 / BN, (NT + BM - 1) / BM);
        gemm_kernel<<<grid, 256, GEMM_SMEM>>>(p_A1, p_Wt1, p_xh1, NT, F1, 256);
    }
    alpha1_kernel<<<(NT * 32 + 255) / 256, 256>>>(att_src1, att_dst1);

    // ---- join CSR, then aggregate ----
    cudaStreamWaitEvent(0, evJoin, 0);
    agg1_kernel<<<(NT * HH * 32 + 255) / 256, 256>>>(b1);

    // layer-2 GEMM
    {
        dim3 grid(FOUT / BN, (NT + BM - 1) / BM);
        gemm_kernel<<<grid, 256, GEMM_SMEM>>>(p_A2, p_Wt2, p_xh2, NT, FOUT, 512);
    }
    alpha2_kernel<<<(NT * 32 + 255) / 256, 256>>>(att_src2, att_dst2);
    agg2_kernel<<<(NT * 32 + 255) / 256, 256>>>(b2, out);
}

// round 11
// speedup vs baseline: 2.2156x; 1.6127x over previous
#include <cuda_runtime.h>
#include <cuda_bf16.h>
#include <cuda_fp16.h>
#include <math.h>
#include <stdint.h>

// ---------------- problem constants ----------------
#define BB   2
#define NN   10000
#define NT   20000           // BB*NN nodes
#define EE   160000          // edges per graph
#define EB   320000          // BB*EE batched edges
#define ET   340000          // EB + NT self loops
#define FIN  256
#define HID  256
#define HH   2
#define F1   512             // HH*HID
#define FOUT 256
#define NEG_SLOPE 0.2f

// ---------------- device scratch ----------------
__device__ __half g_xh1[(size_t)NT * F1];            // fp16 xw1 (gathers + alphas)
__device__ __half g_xh2[(size_t)NT * FOUT];          // fp16 xw2 (gathers + alphas)
__device__ __half g_A1h[(size_t)NT * FIN];           // fp16 x
__device__ __half g_A2h[(size_t)NT * F1];            // fp16 h (layer-2 GEMM input)
__device__ __half g_Wt1h[(size_t)512 * 256];         // W1^T fp16: [n=512][k=256]
__device__ __half g_Wt2h[(size_t)256 * 512];         // W2^T fp16: [n=256][k=512]
__device__ float g_as1[NT * HH];
__device__ float g_ad1[NT * HH];
__device__ float g_as2[NT];
__device__ float g_ad2[NT];
__device__ int   g_cnt[NT + 1];
__device__ int   g_off[NT + 1];
__device__ int   g_srcidx[ET];

// ---------------- helpers ----------------
__device__ __forceinline__ uint32_t smem_u32(const void* p) {
    return (uint32_t)__cvta_generic_to_shared(p);
}
__device__ __forceinline__ void cp16(uint32_t dst, const void* src, int src_sz) {
    asm volatile("cp.async.cg.shared.global [%0], [%1], 16, %2;"
                 :: "r"(dst), "l"(src), "r"(src_sz) : "memory");
}
__device__ __forceinline__ void cp_commit() {
    asm volatile("cp.async.commit_group;" ::: "memory");
}
template <int N>
__device__ __forceinline__ void cp_wait() {
    asm volatile("cp.async.wait_group %0;" :: "n"(N) : "memory");
}
__device__ __forceinline__ void ldm4(uint32_t* r, uint32_t addr) {
    asm volatile("ldmatrix.sync.aligned.m8n8.x4.shared.b16 {%0,%1,%2,%3}, [%4];"
                 : "=r"(r[0]), "=r"(r[1]), "=r"(r[2]), "=r"(r[3]) : "r"(addr));
}
__device__ __forceinline__ void mma16816h(float* c, const uint32_t* a, const uint32_t* b) {
    asm volatile(
        "mma.sync.aligned.m16n8k16.row.col.f32.f16.f16.f32 "
        "{%0,%1,%2,%3}, {%4,%5,%6,%7}, {%8,%9}, {%0,%1,%2,%3};"
        : "+f"(c[0]), "+f"(c[1]), "+f"(c[2]), "+f"(c[3])
        : "r"(a[0]), "r"(a[1]), "r"(a[2]), "r"(a[3]), "r"(b[0]), "r"(b[1]));
}
// XOR swizzle: 64B rows, chunk' = chunk ^ ((row>>1)&3); conflict-free ldmatrix, 16B-aligned
__device__ __forceinline__ uint32_t swz(int row, int cByte) {
    return (uint32_t)(row * 64 + (cByte ^ ((((row >> 1) & 3)) << 4)));
}

// ---------------- fp16 mma.sync GEMM, 4-stage cp.async, BKr=32 ----------------
// C = A @ Bt^T, both fp16 K-major, fp32 accumulate, fp16 output.
#define BM 128
#define BN 128
#define BKr 32
#define TILE_B (128 * 64)            // 8192 bytes per tile (32 halfs/row, swizzled)
#define STAGE_B (2 * TILE_B)         // A, B = 16384
#define NSTG 4
#define GEMM_SMEM (NSTG * STAGE_B)   // 65536 bytes

__global__ __launch_bounds__(256, 2)
void gemm_kernel(const __half* __restrict__ A,
                 const __half* __restrict__ Bt,
                 __half* __restrict__ Ch, int M, int N, int K) {
    extern __shared__ char sm[];
    const int tid = threadIdx.x;
    const int lane = tid & 31;
    const int wid = tid >> 5;
    const int wm = wid & 3;          // 4 warps over M (32 rows each)
    const int wn = wid >> 2;         // 2 warps over N (64 cols each)
    const int m0 = blockIdx.y * BM;
    const int n0 = blockIdx.x * BN;
    const uint32_t sbase = smem_u32(sm);

    float acc[2][8][4];
#pragma unroll
    for (int i = 0; i < 2; i++)
#pragma unroll
        for (int j = 0; j < 8; j++)
#pragma unroll
            for (int t = 0; t < 4; t++) acc[i][j][t] = 0.f;

    // loader: row = tid>>1 (0..127), 32B half of 64B row = tid&1
    const int lrow = tid >> 1;
    const int cb = (tid & 1) * 32;
    const uint32_t sw0 = swz(lrow, cb);
    const uint32_t sw1 = swz(lrow, cb + 16);
    const int ke = (tid & 1) * 16;               // element (half) offset in 32-elem slab
    const __half* gA = A + (size_t)(m0 + lrow) * K;
    const __half* gB = Bt + (size_t)(n0 + lrow) * K;
    const int a_ok = (m0 + lrow) < M ? 16 : 0;

    const int NIT = K / BKr;

    auto issue = [&](int it) {
        const int s = it & (NSTG - 1);
        const int k0 = it * BKr + ke;
        uint32_t d = sbase + s * STAGE_B;
        cp16(d + sw0,          gA + k0,     a_ok);
        cp16(d + sw1,          gA + k0 + 8, a_ok);
        cp16(d + TILE_B + sw0, gB + k0,     16);
        cp16(d + TILE_B + sw1, gB + k0 + 8, 16);
        cp_commit();
    };

    issue(0); issue(1); issue(2);

    const int arow = wm * 32 + (lane & 15);
    const int acb = (lane >> 4) * 16;
    const int brow = wn * 64 + (lane & 7) + ((lane >> 4) << 3);
    const int bcb = ((lane >> 3) & 1) * 16;

    for (int it = 0; it < NIT; it++) {
        const int s = it & (NSTG - 1);
        cp_wait<NSTG - 2>();
        __syncthreads();
        if (it + 3 < NIT) issue(it + 3); else cp_commit();

        const uint32_t base = sbase + s * STAGE_B;
#pragma unroll
        for (int k16 = 0; k16 < 2; k16++) {
            const int kc = acb + k16 * 32;
            uint32_t a[2][4];
#pragma unroll
            for (int mf = 0; mf < 2; mf++)
                ldm4(a[mf], base + swz(arow + mf * 16, kc));
            const int kb = bcb + k16 * 32;
#pragma unroll
            for (int ng = 0; ng < 4; ng++) {
                uint32_t b[4];
                ldm4(b, base + TILE_B + swz(brow + ng * 16, kb));
#pragma unroll
                for (int mf = 0; mf < 2; mf++) {
#pragma unroll
                    for (int t = 0; t < 2; t++)
                        mma16816h(acc[mf][ng * 2 + t], a[mf], b + 2 * t);
                }
            }
        }
    }

    // epilogue: fp16 store
#pragma unroll
    for (int mf = 0; mf < 2; mf++) {
        const int mA = m0 + wm * 32 + mf * 16 + (lane >> 2);
        const int mB = mA + 8;
#pragma unroll
        for (int nf = 0; nf < 8; nf++) {
            const int n = n0 + wn * 64 + nf * 8 + (lane & 3) * 2;
            const float* c = acc[mf][nf];
            if (mA < M) *(__half2*)(Ch + (size_t)mA * N + n) = __floats2half2_rn(c[0], c[1]);
            if (mB < M) *(__half2*)(Ch + (size_t)mB * N + n) = __floats2half2_rn(c[2], c[3]);
        }
    }
}

// ---------------- conversion kernels ----------------
__global__ void conv_x_kernel(const float* __restrict__ x) {
    int i = blockIdx.x * blockDim.x + threadIdx.x;
    if (i >= NT * 128) return;
    int row = i >> 7;
    int c2 = (i & 127) << 1;
    float2 f = *(const float2*)(x + (size_t)row * FIN + c2);
    *(__half2*)(g_A1h + (size_t)row * FIN + c2) = __floats2half2_rn(f.x, f.y);
}

__global__ void conv_w1_kernel(const float* __restrict__ W1) {
    int i = blockIdx.x * blockDim.x + threadIdx.x;   // over 512*256
    if (i >= 512 * 256) return;
    int n = i >> 8, k = i & 255;
    g_Wt1h[i] = __float2half(W1[(size_t)k * F1 + n]);
}

__global__ void conv_w2_kernel(const float* __restrict__ W2) {
    int i = blockIdx.x * blockDim.x + threadIdx.x;   // over 256*512
    if (i >= 256 * 512) return;
    int n = i >> 9, k = i & 511;
    g_Wt2h[i] = __float2half(W2[(size_t)k * FOUT + n]);
}

// ---------------- edge enumeration ----------------
__device__ __forceinline__ void edge_sd(int j, const int* ei, int& s, int& d) {
    if (j < EB) {
        int b = j / EE;
        int k = j - b * EE;
        s = ei[k]      + b * NN;
        d = ei[EE + k] + b * NN;
    } else {
        s = d = j - EB;
    }
}

// ---------------- alphas: warp per node, fp16 reads ----------------
__global__ void alpha1_kernel(const float* __restrict__ att_src,
                              const float* __restrict__ att_dst) {
    int gid = blockIdx.x * blockDim.x + threadIdx.x;
    int w = gid >> 5;
    int lane = gid & 31;
    if (w >= NT) return;
#pragma unroll
    for (int h = 0; h < HH; h++) {
        uint4 r = *(const uint4*)(g_xh1 + (size_t)w * F1 + h * HID + lane * 8);
        float2 v0 = __half22float2(*(const __half2*)&r.x);
        float2 v1 = __half22float2(*(const __half2*)&r.y);
        float2 v2 = __half22float2(*(const __half2*)&r.z);
        float2 v3 = __half22float2(*(const __half2*)&r.w);
        const float* as = att_src + h * HID + lane * 8;
        const float* ad = att_dst + h * HID + lane * 8;
        float4 s0 = *(const float4*)(as);
        float4 s1 = *(const float4*)(as + 4);
        float4 d0 = *(const float4*)(ad);
        float4 d1 = *(const float4*)(ad + 4);
        float ps = v0.x * s0.x + v0.y * s0.y + v1.x * s0.z + v1.y * s0.w
                 + v2.x * s1.x + v2.y * s1.y + v3.x * s1.z + v3.y * s1.w;
        float pd = v0.x * d0.x + v0.y * d0.y + v1.x * d0.z + v1.y * d0.w
                 + v2.x * d1.x + v2.y * d1.y + v3.x * d1.z + v3.y * d1.w;
#pragma unroll
        for (int o = 16; o > 0; o >>= 1) {
            ps += __shfl_xor_sync(0xffffffffu, ps, o);
            pd += __shfl_xor_sync(0xffffffffu, pd, o);
        }
        if (lane == 0) { g_as1[w * HH + h] = ps; g_ad1[w * HH + h] = pd; }
    }
}

__global__ void alpha2_kernel(const float* __restrict__ att_src,
                              const float* __restrict__ att_dst) {
    int gid = blockIdx.x * blockDim.x + threadIdx.x;
    int w = gid >> 5;
    int lane = gid & 31;
    if (w >= NT) return;
    uint4 r = *(const uint4*)(g_xh2 + (size_t)w * FOUT + lane * 8);
    float2 v0 = __half22float2(*(const __half2*)&r.x);
    float2 v1 = __half22float2(*(const __half2*)&r.y);
    float2 v2 = __half22float2(*(const __half2*)&r.z);
    float2 v3 = __half22float2(*(const __half2*)&r.w);
    const float* as = att_src + lane * 8;
    const float* ad = att_dst + lane * 8;
    float4 s0 = *(const float4*)(as);
    float4 s1 = *(const float4*)(as + 4);
    float4 d0 = *(const float4*)(ad);
    float4 d1 = *(const float4*)(ad + 4);
    float ps = v0.x * s0.x + v0.y * s0.y + v1.x * s0.z + v1.y * s0.w
             + v2.x * s1.x + v2.y * s1.y + v3.x * s1.z + v3.y * s1.w;
    float pd = v0.x * d0.x + v0.y * d0.y + v1.x * d0.z + v1.y * d0.w
             + v2.x * d1.x + v2.y * d1.y + v3.x * d1.z + v3.y * d1.w;
#pragma unroll
    for (int o = 16; o > 0; o >>= 1) {
        ps += __shfl_xor_sync(0xffffffffu, ps, o);
        pd += __shfl_xor_sync(0xffffffffu, pd, o);
    }
    if (lane == 0) { g_as2[w] = ps; g_ad2[w] = pd; }
}

// ---------------- CSR build (forked stream) ----------------
__global__ void zero_cnt_kernel() {
    int i = blockIdx.x * blockDim.x + threadIdx.x;
    if (i <= NT) g_cnt[i] = 0;
}

__global__ void count_kernel(const int* __restrict__ ei) {
    int j = blockIdx.x * blockDim.x + threadIdx.x;
    if (j >= ET) return;
    int s, d;
    edge_sd(j, ei, s, d);
    atomicAdd(&g_cnt[d], 1);
}

__global__ void scan_kernel() {
    __shared__ int warp_base[32];
    int t = threadIdx.x;                 // 1024 threads
    int lane = t & 31, w = t >> 5;
    const int CH = 20;
    int base = t * CH;
    int local[CH];
    int sum = 0;
#pragma unroll
    for (int i = 0; i < CH; i++) {
        int idx = base + i;
        int v = (idx < NT) ? g_cnt[idx] : 0;
        local[i] = v;
        sum += v;
    }
    int inc = sum;
#pragma unroll
    for (int o = 1; o < 32; o <<= 1) {
        int v = __shfl_up_sync(0xffffffffu, inc, o);
        if (lane >= o) inc += v;
    }
    if (lane == 31) warp_base[w] = inc;
    __syncthreads();
    if (t < 32) {
        int v = warp_base[t];
        int wi = v;
#pragma unroll
        for (int o = 1; o < 32; o <<= 1) {
            int u = __shfl_up_sync(0xffffffffu, wi, o);
            if (t >= o) wi += u;
        }
        warp_base[t] = wi - v;
    }
    __syncthreads();
    int run = warp_base[w] + inc - sum;
#pragma unroll
    for (int i = 0; i < CH; i++) {
        int idx = base + i;
        if (idx < NT) { g_off[idx] = run; run += local[i]; }
    }
    if (t == 0) g_off[NT] = ET;
    for (int i = t; i < NT + 1; i += 1024) g_cnt[i] = 0;
}

__global__ void fill_kernel(const int* __restrict__ ei) {
    int j = blockIdx.x * blockDim.x + threadIdx.x;
    if (j >= ET) return;
    int s, d;
    edge_sd(j, ei, s, d);
    int pos = atomicAdd(&g_cnt[d], 1);
    g_srcidx[g_off[d] + pos] = s;
}

// ---------------- layer-1 aggregation: warp per (dst, head), fp16 gather, fp16 h out ----------------
__global__ void agg1_kernel(const float* __restrict__ b1) {
    int w = (blockIdx.x * blockDim.x + threadIdx.x) >> 5;
    int lane = threadIdx.x & 31;
    if (w >= NT * HH) return;
    int d = w >> 1;
    int h = w & 1;
    int beg = g_off[d], end = g_off[d + 1];
    float adh = g_ad1[d * HH + h];

    float acc[8] = {0.f, 0.f, 0.f, 0.f, 0.f, 0.f, 0.f, 0.f};
    float denom = 0.f;
    int j = beg;
    for (; j + 1 < end; j += 2) {
        int s0 = g_srcidx[j];
        int s1 = g_srcidx[j + 1];
        float e0 = g_as1[s0 * HH + h] + adh;
        float e1 = g_as1[s1 * HH + h] + adh;
        uint4 r0 = *(const uint4*)(g_xh1 + (size_t)s0 * F1 + h * HID + lane * 8);
        uint4 r1 = *(const uint4*)(g_xh1 + (size_t)s1 * F1 + h * HID + lane * 8);
        e0 = e0 > 0.f ? e0 : NEG_SLOPE * e0;
        e1 = e1 > 0.f ? e1 : NEG_SLOPE * e1;
        float ex0 = __expf(e0);
        float ex1 = __expf(e1);
        denom += ex0 + ex1;
        float2 a0 = __half22float2(*(const __half2*)&r0.x);
        float2 a1 = __half22float2(*(const __half2*)&r0.y);
        float2 a2 = __half22float2(*(const __half2*)&r0.z);
        float2 a3 = __half22float2(*(const __half2*)&r0.w);
        float2 c0 = __half22float2(*(const __half2*)&r1.x);
        float2 c1 = __half22float2(*(const __half2*)&r1.y);
        float2 c2 = __half22float2(*(const __half2*)&r1.z);
        float2 c3 = __half22float2(*(const __half2*)&r1.w);
        acc[0] += ex0 * a0.x + ex1 * c0.x; acc[1] += ex0 * a0.y + ex1 * c0.y;
        acc[2] += ex0 * a1.x + ex1 * c1.x; acc[3] += ex0 * a1.y + ex1 * c1.y;
        acc[4] += ex0 * a2.x + ex1 * c2.x; acc[5] += ex0 * a2.y + ex1 * c2.y;
        acc[6] += ex0 * a3.x + ex1 * c3.x; acc[7] += ex0 * a3.y + ex1 * c3.y;
    }
    if (j < end) {
        int s0 = g_srcidx[j];
        float e0 = g_as1[s0 * HH + h] + adh;
        e0 = e0 > 0.f ? e0 : NEG_SLOPE * e0;
        float ex0 = __expf(e0);
        denom += ex0;
        uint4 r0 = *(const uint4*)(g_xh1 + (size_t)s0 * F1 + h * HID + lane * 8);
        float2 a0 = __half22float2(*(const __half2*)&r0.x);
        float2 a1 = __half22float2(*(const __half2*)&r0.y);
        float2 a2 = __half22float2(*(const __half2*)&r0.z);
        float2 a3 = __half22float2(*(const __half2*)&r0.w);
        acc[0] += ex0 * a0.x; acc[1] += ex0 * a0.y;
        acc[2] += ex0 * a1.x; acc[3] += ex0 * a1.y;
        acc[4] += ex0 * a2.x; acc[5] += ex0 * a2.y;
        acc[6] += ex0 * a3.x; acc[7] += ex0 * a3.y;
    }
    float inv = 1.f / (denom + 1e-16f);
    float v[8];
#pragma unroll
    for (int k = 0; k < 8; k++) {
        int c = lane * 8 + k;
        float t = acc[k] * inv + b1[h * HID + c];
        v[k] = 0.5f * t * (1.f + erff(t * 0.70710678118654752f));   // exact gelu
    }
    __half2 o0 = __floats2half2_rn(v[0], v[1]);
    __half2 o1 = __floats2half2_rn(v[2], v[3]);
    __half2 o2 = __floats2half2_rn(v[4], v[5]);
    __half2 o3 = __floats2half2_rn(v[6], v[7]);
    uint4 pack;
    pack.x = *(uint32_t*)&o0; pack.y = *(uint32_t*)&o1;
    pack.z = *(uint32_t*)&o2; pack.w = *(uint32_t*)&o3;
    *(uint4*)(g_A2h + (size_t)d * F1 + h * HID + lane * 8) = pack;
}

// ---------------- layer-2 aggregation: warp per dst, fp16 gather ----------------
__global__ void agg2_kernel(const float* __restrict__ b2, float* __restrict__ out) {
    int d = (blockIdx.x * blockDim.x + threadIdx.x) >> 5;
    int lane = threadIdx.x & 31;
    if (d >= NT) return;
    int beg = g_off[d], end = g_off[d + 1];
    float adh = g_ad2[d];

    float acc[8] = {0.f, 0.f, 0.f, 0.f, 0.f, 0.f, 0.f, 0.f};
    float denom = 0.f;
    int j = beg;
    for (; j + 1 < end; j += 2) {
        int s0 = g_srcidx[j];
        int s1 = g_srcidx[j + 1];
        float e0 = g_as2[s0] + adh;
        float e1 = g_as2[s1] + adh;
        uint4 r0 = *(const uint4*)(g_xh2 + (size_t)s0 * FOUT + lane * 8);
        uint4 r1 = *(const uint4*)(g_xh2 + (size_t)s1 * FOUT + lane * 8);
        e0 = e0 > 0.f ? e0 : NEG_SLOPE * e0;
        e1 = e1 > 0.f ? e1 : NEG_SLOPE * e1;
        float ex0 = __expf(e0);
        float ex1 = __expf(e1);
        denom += ex0 + ex1;
        float2 a0 = __half22float2(*(const __half2*)&r0.x);
        float2 a1 = __half22float2(*(const __half2*)&r0.y);
        float2 a2 = __half22float2(*(const __half2*)&r0.z);
        float2 a3 = __half22float2(*(const __half2*)&r0.w);
        float2 c0 = __half22float2(*(const __half2*)&r1.x);
        float2 c1 = __half22float2(*(const __half2*)&r1.y);
        float2 c2 = __half22float2(*(const __half2*)&r1.z);
        float2 c3 = __half22float2(*(const __half2*)&r1.w);
        acc[0] += ex0 * a0.x + ex1 * c0.x; acc[1] += ex0 * a0.y + ex1 * c0.y;
        acc[2] += ex0 * a1.x + ex1 * c1.x; acc[3] += ex0 * a1.y + ex1 * c1.y;
        acc[4] += ex0 * a2.x + ex1 * c2.x; acc[5] += ex0 * a2.y + ex1 * c2.y;
        acc[6] += ex0 * a3.x + ex1 * c3.x; acc[7] += ex0 * a3.y + ex1 * c3.y;
    }
    if (j < end) {
        int s0 = g_srcidx[j];
        float e0 = g_as2[s0] + adh;
        e0 = e0 > 0.f ? e0 : NEG_SLOPE * e0;
        float ex0 = __expf(e0);
        denom += ex0;
        uint4 r0 = *(const uint4*)(g_xh2 + (size_t)s0 * FOUT + lane * 8);
        float2 a0 = __half22float2(*(const __half2*)&r0.x);
        float2 a1 = __half22float2(*(const __half2*)&r0.y);
        float2 a2 = __half22float2(*(const __half2*)&r0.z);
        float2 a3 = __half22float2(*(const __half2*)&r0.w);
        acc[0] += ex0 * a0.x; acc[1] += ex0 * a0.y;
        acc[2] += ex0 * a1.x; acc[3] += ex0 * a1.y;
        acc[4] += ex0 * a2.x; acc[5] += ex0 * a2.y;
        acc[6] += ex0 * a3.x; acc[7] += ex0 * a3.y;
    }
    float inv = 1.f / (denom + 1e-16f);
    float* outp = out + (size_t)d * FOUT + lane * 8;
    float4 o0 = make_float4(acc[0] * inv + b2[lane * 8 + 0],
                            acc[1] * inv + b2[lane * 8 + 1],
                            acc[2] * inv + b2[lane * 8 + 2],
                            acc[3] * inv + b2[lane * 8 + 3]);
    float4 o1 = make_float4(acc[4] * inv + b2[lane * 8 + 4],
                            acc[5] * inv + b2[lane * 8 + 5],
                            acc[6] * inv + b2[lane * 8 + 6],
                            acc[7] * inv + b2[lane * 8 + 7]);
    *(float4*)(outp) = o0;
    *(float4*)(outp + 4) = o1;
}

// ---------------- launch ----------------
extern "C" void kernel_launch(void* const* d_in, const int* in_sizes, int n_in,
                              void* d_out, int out_size) {
    const float* x        = (const float*)d_in[0];
    const int*   ei       = (const int*)  d_in[1];
    const float* W1       = (const float*)d_in[2];
    const float* att_src1 = (const float*)d_in[3];
    const float* att_dst1 = (const float*)d_in[4];
    const float* b1       = (const float*)d_in[5];
    const float* W2       = (const float*)d_in[6];
    const float* att_src2 = (const float*)d_in[7];
    const float* att_dst2 = (const float*)d_in[8];
    const float* b2       = (const float*)d_in[9];
    float* out = (float*)d_out;

    __half *p_xh1, *p_xh2, *p_A1h, *p_A2h, *p_Wt1h, *p_Wt2h;
    cudaGetSymbolAddress((void**)&p_xh1,  g_xh1);
    cudaGetSymbolAddress((void**)&p_xh2,  g_xh2);
    cudaGetSymbolAddress((void**)&p_A1h,  g_A1h);
    cudaGetSymbolAddress((void**)&p_A2h,  g_A2h);
    cudaGetSymbolAddress((void**)&p_Wt1h, g_Wt1h);
    cudaGetSymbolAddress((void**)&p_Wt2h, g_Wt2h);

    static cudaStream_t s2 = nullptr;
    static cudaEvent_t evFork = nullptr, evJoin = nullptr;
    if (!s2) {
        cudaStreamCreateWithFlags(&s2, cudaStreamNonBlocking);
        cudaEventCreateWithFlags(&evFork, cudaEventDisableTiming);
        cudaEventCreateWithFlags(&evJoin, cudaEventDisableTiming);
        cudaFuncSetAttribute(gemm_kernel, cudaFuncAttributeMaxDynamicSharedMemorySize, GEMM_SMEM);
    }

    // ---- fork: CSR build + conv_w2 on s2 ----
    cudaEventRecord(evFork, 0);
    cudaStreamWaitEvent(s2, evFork, 0);
    zero_cnt_kernel<<<(NT + 256) / 256, 256, 0, s2>>>();
    count_kernel<<<(ET + 255) / 256, 256, 0, s2>>>(ei);
    scan_kernel<<<1, 1024, 0, s2>>>();
    fill_kernel<<<(ET + 255) / 256, 256, 0, s2>>>(ei);
    conv_w2_kernel<<<(256 * 512 + 255) / 256, 256, 0, s2>>>(W2);
    cudaEventRecord(evJoin, s2);

    // ---- main: conversions + layer-1 GEMM + alpha1 ----
    conv_x_kernel<<<(NT * 128 + 255) / 256, 256>>>(x);
    conv_w1_kernel<<<(512 * 256 + 255) / 256, 256>>>(W1);
    {
        dim3 grid(F1 / BN, (NT + BM - 1) / BM);
        gemm_kernel<<<grid, 256, GEMM_SMEM>>>(p_A1h, p_Wt1h, p_xh1, NT, F1, 256);
    }
    alpha1_kernel<<<(NT * 32 + 255) / 256, 256>>>(att_src1, att_dst1);

    // ---- join CSR, then aggregate ----
    cudaStreamWaitEvent(0, evJoin, 0);
    agg1_kernel<<<(NT * HH * 32 + 255) / 256, 256>>>(b1);

    // layer-2 GEMM (fp16, K=512)
    {
        dim3 grid(FOUT / BN, (NT + BM - 1) / BM);
        gemm_kernel<<<grid, 256, GEMM_SMEM>>>(p_A2h, p_Wt2h, p_xh2, NT, FOUT, 512);
    }
    alpha2_kernel<<<(NT * 32 + 255) / 256, 256>>>(att_src2, att_dst2);
    agg2_kernel<<<(NT * 32 + 255) / 256, 256>>>(b2, out);
}

// round 13
// speedup vs baseline: 2.2750x; 1.0268x over previous
#include <cuda_runtime.h>
#include <cuda_bf16.h>
#include <cuda_fp16.h>
#include <math.h>
#include <stdint.h>

// ---------------- problem constants ----------------
#define BB   2
#define NN   10000
#define NT   20000           // BB*NN nodes
#define EE   160000          // edges per graph
#define EB   320000          // BB*EE batched edges
#define ET   340000          // EB + NT self loops
#define FIN  256
#define HID  256
#define HH   2
#define F1   512             // HH*HID
#define FOUT 256
#define NEG_SLOPE 0.2f

// ---------------- device scratch ----------------
__device__ __half g_xh1[(size_t)NT * F1];            // fp16 xw1 (gathers + alphas)
__device__ __half g_xh2[(size_t)NT * FOUT];          // fp16 xw2 (gathers + alphas)
__device__ __half g_A1h[(size_t)NT * FIN];           // fp16 x
__device__ __half g_A2h[(size_t)NT * F1];            // fp16 h (layer-2 GEMM input)
__device__ __half g_Wt1h[(size_t)512 * 256];         // W1^T fp16: [n=512][k=256]
__device__ __half g_Wt2h[(size_t)256 * 512];         // W2^T fp16: [n=256][k=512]
__device__ float g_as1[NT * HH];
__device__ float g_ad1[NT * HH];
__device__ float g_as2[NT];
__device__ float g_ad2[NT];
__device__ int   g_cnt[NT + 1];
__device__ int   g_off[NT + 1];
__device__ int   g_srcidx[ET];

// ---------------- helpers ----------------
__device__ __forceinline__ uint32_t smem_u32(const void* p) {
    return (uint32_t)__cvta_generic_to_shared(p);
}
__device__ __forceinline__ void cp16(uint32_t dst, const void* src, int src_sz) {
    asm volatile("cp.async.cg.shared.global [%0], [%1], 16, %2;"
                 :: "r"(dst), "l"(src), "r"(src_sz) : "memory");
}
__device__ __forceinline__ void cp_commit() {
    asm volatile("cp.async.commit_group;" ::: "memory");
}
template <int N>
__device__ __forceinline__ void cp_wait() {
    asm volatile("cp.async.wait_group %0;" :: "n"(N) : "memory");
}
__device__ __forceinline__ void ldm4(uint32_t* r, uint32_t addr) {
    asm volatile("ldmatrix.sync.aligned.m8n8.x4.shared.b16 {%0,%1,%2,%3}, [%4];"
                 : "=r"(r[0]), "=r"(r[1]), "=r"(r[2]), "=r"(r[3]) : "r"(addr));
}
__device__ __forceinline__ void mma16816h(float* c, const uint32_t* a, const uint32_t* b) {
    asm volatile(
        "mma.sync.aligned.m16n8k16.row.col.f32.f16.f16.f32 "
        "{%0,%1,%2,%3}, {%4,%5,%6,%7}, {%8,%9}, {%0,%1,%2,%3};"
        : "+f"(c[0]), "+f"(c[1]), "+f"(c[2]), "+f"(c[3])
        : "r"(a[0]), "r"(a[1]), "r"(a[2]), "r"(a[3]), "r"(b[0]), "r"(b[1]));
}
// XOR swizzle: 64B rows, chunk' = chunk ^ ((row>>1)&3); conflict-free ldmatrix, 16B-aligned
__device__ __forceinline__ uint32_t swz(int row, int cByte) {
    return (uint32_t)(row * 64 + (cByte ^ ((((row >> 1) & 3)) << 4)));
}
__device__ __forceinline__ float lrelu(float e) {
    return e > 0.f ? e : NEG_SLOPE * e;
}
__device__ __forceinline__ void acc8(float* acc, const uint4& r, float ex) {
    float2 a0 = __half22float2(*(const __half2*)&r.x);
    float2 a1 = __half22float2(*(const __half2*)&r.y);
    float2 a2 = __half22float2(*(const __half2*)&r.z);
    float2 a3 = __half22float2(*(const __half2*)&r.w);
    acc[0] += ex * a0.x; acc[1] += ex * a0.y;
    acc[2] += ex * a1.x; acc[3] += ex * a1.y;
    acc[4] += ex * a2.x; acc[5] += ex * a2.y;
    acc[6] += ex * a3.x; acc[7] += ex * a3.y;
}

// ---------------- fp16 mma.sync GEMM, 4-stage cp.async, BKr=32 ----------------
#define BM 128
#define BN 128
#define BKr 32
#define TILE_B (128 * 64)            // 8192 bytes per tile (32 halfs/row, swizzled)
#define STAGE_B (2 * TILE_B)         // A, B = 16384
#define NSTG 4
#define GEMM_SMEM (NSTG * STAGE_B)   // 65536 bytes

__global__ __launch_bounds__(256, 2)
void gemm_kernel(const __half* __restrict__ A,
                 const __half* __restrict__ Bt,
                 __half* __restrict__ Ch, int M, int N, int K) {
    extern __shared__ char sm[];
    const int tid = threadIdx.x;
    const int lane = tid & 31;
    const int wid = tid >> 5;
    const int wm = wid & 3;
    const int wn = wid >> 2;
    const int m0 = blockIdx.y * BM;
    const int n0 = blockIdx.x * BN;
    const uint32_t sbase = smem_u32(sm);

    float acc[2][8][4];
#pragma unroll
    for (int i = 0; i < 2; i++)
#pragma unroll
        for (int j = 0; j < 8; j++)
#pragma unroll
            for (int t = 0; t < 4; t++) acc[i][j][t] = 0.f;

    const int lrow = tid >> 1;
    const int cb = (tid & 1) * 32;
    const uint32_t sw0 = swz(lrow, cb);
    const uint32_t sw1 = swz(lrow, cb + 16);
    const int ke = (tid & 1) * 16;
    const __half* gA = A + (size_t)(m0 + lrow) * K;
    const __half* gB = Bt + (size_t)(n0 + lrow) * K;
    const int a_ok = (m0 + lrow) < M ? 16 : 0;

    const int NIT = K / BKr;

    auto issue = [&](int it) {
        const int s = it & (NSTG - 1);
        const int k0 = it * BKr + ke;
        uint32_t d = sbase + s * STAGE_B;
        cp16(d + sw0,          gA + k0,     a_ok);
        cp16(d + sw1,          gA + k0 + 8, a_ok);
        cp16(d + TILE_B + sw0, gB + k0,     16);
        cp16(d + TILE_B + sw1, gB + k0 + 8, 16);
        cp_commit();
    };

    issue(0); issue(1); issue(2);

    const int arow = wm * 32 + (lane & 15);
    const int acb = (lane >> 4) * 16;
    const int brow = wn * 64 + (lane & 7) + ((lane >> 4) << 3);
    const int bcb = ((lane >> 3) & 1) * 16;

    for (int it = 0; it < NIT; it++) {
        const int s = it & (NSTG - 1);
        cp_wait<NSTG - 2>();
        __syncthreads();
        if (it + 3 < NIT) issue(it + 3); else cp_commit();

        const uint32_t base = sbase + s * STAGE_B;
#pragma unroll
        for (int k16 = 0; k16 < 2; k16++) {
            const int kc = acb + k16 * 32;
            uint32_t a[2][4];
#pragma unroll
            for (int mf = 0; mf < 2; mf++)
                ldm4(a[mf], base + swz(arow + mf * 16, kc));
            const int kb = bcb + k16 * 32;
#pragma unroll
            for (int ng = 0; ng < 4; ng++) {
                uint32_t b[4];
                ldm4(b, base + TILE_B + swz(brow + ng * 16, kb));
#pragma unroll
                for (int mf = 0; mf < 2; mf++) {
#pragma unroll
                    for (int t = 0; t < 2; t++)
                        mma16816h(acc[mf][ng * 2 + t], a[mf], b + 2 * t);
                }
            }
        }
    }

#pragma unroll
    for (int mf = 0; mf < 2; mf++) {
        const int mA = m0 + wm * 32 + mf * 16 + (lane >> 2);
        const int mB = mA + 8;
#pragma unroll
        for (int nf = 0; nf < 8; nf++) {
            const int n = n0 + wn * 64 + nf * 8 + (lane & 3) * 2;
            const float* c = acc[mf][nf];
            if (mA < M) *(__half2*)(Ch + (size_t)mA * N + n) = __floats2half2_rn(c[0], c[1]);
            if (mB < M) *(__half2*)(Ch + (size_t)mB * N + n) = __floats2half2_rn(c[2], c[3]);
        }
    }
}

// ---------------- conversion kernels ----------------
__global__ void conv_x_kernel(const float* __restrict__ x) {
    int i = blockIdx.x * blockDim.x + threadIdx.x;
    if (i >= NT * 128) return;
    int row = i >> 7;
    int c2 = (i & 127) << 1;
    float2 f = *(const float2*)(x + (size_t)row * FIN + c2);
    *(__half2*)(g_A1h + (size_t)row * FIN + c2) = __floats2half2_rn(f.x, f.y);
}

__global__ void conv_w1_kernel(const float* __restrict__ W1) {
    int i = blockIdx.x * blockDim.x + threadIdx.x;   // over 512*256
    if (i >= 512 * 256) return;
    int n = i >> 8, k = i & 255;
    g_Wt1h[i] = __float2half(W1[(size_t)k * F1 + n]);
}

__global__ void conv_w2_kernel(const float* __restrict__ W2) {
    int i = blockIdx.x * blockDim.x + threadIdx.x;   // over 256*512
    if (i >= 256 * 512) return;
    int n = i >> 9, k = i & 511;
    g_Wt2h[i] = __float2half(W2[(size_t)k * FOUT + n]);
}

// ---------------- edge enumeration ----------------
__device__ __forceinline__ void edge_sd(int j, const int* ei, int& s, int& d) {
    if (j < EB) {
        int b = j / EE;
        int k = j - b * EE;
        s = ei[k]      + b * NN;
        d = ei[EE + k] + b * NN;
    } else {
        s = d = j - EB;
    }
}

// ---------------- alphas: warp per node, fp16 reads ----------------
__global__ void alpha1_kernel(const float* __restrict__ att_src,
                              const float* __restrict__ att_dst) {
    int gid = blockIdx.x * blockDim.x + threadIdx.x;
    int w = gid >> 5;
    int lane = gid & 31;
    if (w >= NT) return;
#pragma unroll
    for (int h = 0; h < HH; h++) {
        uint4 r = *(const uint4*)(g_xh1 + (size_t)w * F1 + h * HID + lane * 8);
        float2 v0 = __half22float2(*(const __half2*)&r.x);
        float2 v1 = __half22float2(*(const __half2*)&r.y);
        float2 v2 = __half22float2(*(const __half2*)&r.z);
        float2 v3 = __half22float2(*(const __half2*)&r.w);
        const float* as = att_src + h * HID + lane * 8;
        const float* ad = att_dst + h * HID + lane * 8;
        float4 s0 = *(const float4*)(as);
        float4 s1 = *(const float4*)(as + 4);
        float4 d0 = *(const float4*)(ad);
        float4 d1 = *(const float4*)(ad + 4);
        float ps = v0.x * s0.x + v0.y * s0.y + v1.x * s0.z + v1.y * s0.w
                 + v2.x * s1.x + v2.y * s1.y + v3.x * s1.z + v3.y * s1.w;
        float pd = v0.x * d0.x + v0.y * d0.y + v1.x * d0.z + v1.y * d0.w
                 + v2.x * d1.x + v2.y * d1.y + v3.x * d1.z + v3.y * d1.w;
#pragma unroll
        for (int o = 16; o > 0; o >>= 1) {
            ps += __shfl_xor_sync(0xffffffffu, ps, o);
            pd += __shfl_xor_sync(0xffffffffu, pd, o);
        }
        if (lane == 0) { g_as1[w * HH + h] = ps; g_ad1[w * HH + h] = pd; }
    }
}

__global__ void alpha2_kernel(const float* __restrict__ att_src,
                              const float* __restrict__ att_dst) {
    int gid = blockIdx.x * blockDim.x + threadIdx.x;
    int w = gid >> 5;
    int lane = gid & 31;
    if (w >= NT) return;
    uint4 r = *(const uint4*)(g_xh2 + (size_t)w * FOUT + lane * 8);
    float2 v0 = __half22float2(*(const __half2*)&r.x);
    float2 v1 = __half22float2(*(const __half2*)&r.y);
    float2 v2 = __half22float2(*(const __half2*)&r.z);
    float2 v3 = __half22float2(*(const __half2*)&r.w);
    const float* as = att_src + lane * 8;
    const float* ad = att_dst + lane * 8;
    float4 s0 = *(const float4*)(as);
    float4 s1 = *(const float4*)(as + 4);
    float4 d0 = *(const float4*)(ad);
    float4 d1 = *(const float4*)(ad + 4);
    float ps = v0.x * s0.x + v0.y * s0.y + v1.x * s0.z + v1.y * s0.w
             + v2.x * s1.x + v2.y * s1.y + v3.x * s1.z + v3.y * s1.w;
    float pd = v0.x * d0.x + v0.y * d0.y + v1.x * d0.z + v1.y * d0.w
             + v2.x * d1.x + v2.y * d1.y + v3.x * d1.z + v3.y * d1.w;
#pragma unroll
    for (int o = 16; o > 0; o >>= 1) {
        ps += __shfl_xor_sync(0xffffffffu, ps, o);
        pd += __shfl_xor_sync(0xffffffffu, pd, o);
    }
    if (lane == 0) { g_as2[w] = ps; g_ad2[w] = pd; }
}

// ---------------- CSR build (forked stream) ----------------
__global__ void zero_cnt_kernel() {
    int i = blockIdx.x * blockDim.x + threadIdx.x;
    if (i <= NT) g_cnt[i] = 0;
}

__global__ void count_kernel(const int* __restrict__ ei) {
    int j = blockIdx.x * blockDim.x + threadIdx.x;
    if (j >= ET) return;
    int s, d;
    edge_sd(j, ei, s, d);
    atomicAdd(&g_cnt[d], 1);
}

__global__ void scan_kernel() {
    __shared__ int warp_base[32];
    int t = threadIdx.x;
    int lane = t & 31, w = t >> 5;
    const int CH = 20;
    int base = t * CH;
    int local[CH];
    int sum = 0;
#pragma unroll
    for (int i = 0; i < CH; i++) {
        int idx = base + i;
        int v = (idx < NT) ? g_cnt[idx] : 0;
        local[i] = v;
        sum += v;
    }
    int inc = sum;
#pragma unroll
    for (int o = 1; o < 32; o <<= 1) {
        int v = __shfl_up_sync(0xffffffffu, inc, o);
        if (lane >= o) inc += v;
    }
    if (lane == 31) warp_base[w] = inc;
    __syncthreads();
    if (t < 32) {
        int v = warp_base[t];
        int wi = v;
#pragma unroll
        for (int o = 1; o < 32; o <<= 1) {
            int u = __shfl_up_sync(0xffffffffu, wi, o);
            if (t >= o) wi += u;
        }
        warp_base[t] = wi - v;
    }
    __syncthreads();
    int run = warp_base[w] + inc - sum;
#pragma unroll
    for (int i = 0; i < CH; i++) {
        int idx = base + i;
        if (idx < NT) { g_off[idx] = run; run += local[i]; }
    }
    if (t == 0) g_off[NT] = ET;
    for (int i = t; i < NT + 1; i += 1024) g_cnt[i] = 0;
}

__global__ void fill_kernel(const int* __restrict__ ei) {
    int j = blockIdx.x * blockDim.x + threadIdx.x;
    if (j >= ET) return;
    int s, d;
    edge_sd(j, ei, s, d);
    int pos = atomicAdd(&g_cnt[d], 1);
    g_srcidx[g_off[d] + pos] = s;
}

// ---------------- layer-1 aggregation: warp per dst, BOTH heads, 2-edge unroll ----------------
__global__ void agg1_kernel(const float* __restrict__ b1) {
    int d = (blockIdx.x * blockDim.x + threadIdx.x) >> 5;
    int lane = threadIdx.x & 31;
    if (d >= NT) return;
    int beg = g_off[d], end = g_off[d + 1];
    float2 ad = *(const float2*)(g_ad1 + d * 2);

    float acc0[8] = {0.f, 0.f, 0.f, 0.f, 0.f, 0.f, 0.f, 0.f};
    float acc1[8] = {0.f, 0.f, 0.f, 0.f, 0.f, 0.f, 0.f, 0.f};
    float den0 = 0.f, den1 = 0.f;
    int j = beg;
    for (; j + 1 < end; j += 2) {
        int s0 = g_srcidx[j];
        int s1 = g_srcidx[j + 1];
        float2 as0 = *(const float2*)(g_as1 + s0 * 2);
        float2 as1v = *(const float2*)(g_as1 + s1 * 2);
        const __half* p0 = g_xh1 + (size_t)s0 * F1 + lane * 8;
        const __half* p1 = g_xh1 + (size_t)s1 * F1 + lane * 8;
        uint4 rA0 = *(const uint4*)(p0);          // s0 head0
        uint4 rB0 = *(const uint4*)(p0 + HID);    // s0 head1
        uint4 rA1 = *(const uint4*)(p1);          // s1 head0
        uint4 rB1 = *(const uint4*)(p1 + HID);    // s1 head1
        float ex00 = __expf(lrelu(as0.x + ad.x));
        float ex01 = __expf(lrelu(as0.y + ad.y));
        float ex10 = __expf(lrelu(as1v.x + ad.x));
        float ex11 = __expf(lrelu(as1v.y + ad.y));
        den0 += ex00 + ex10;
        den1 += ex01 + ex11;
        acc8(acc0, rA0, ex00);
        acc8(acc1, rB0, ex01);
        acc8(acc0, rA1, ex10);
        acc8(acc1, rB1, ex11);
    }
    if (j < end) {
        int s0 = g_srcidx[j];
        float2 as0 = *(const float2*)(g_as1 + s0 * 2);
        const __half* p0 = g_xh1 + (size_t)s0 * F1 + lane * 8;
        uint4 rA0 = *(const uint4*)(p0);
        uint4 rB0 = *(const uint4*)(p0 + HID);
        float ex00 = __expf(lrelu(as0.x + ad.x));
        float ex01 = __expf(lrelu(as0.y + ad.y));
        den0 += ex00;
        den1 += ex01;
        acc8(acc0, rA0, ex00);
        acc8(acc1, rB0, ex01);
    }
    float inv0 = 1.f / (den0 + 1e-16f);
    float inv1 = 1.f / (den1 + 1e-16f);
    float v0[8], v1[8];
#pragma unroll
    for (int k = 0; k < 8; k++) {
        int c = lane * 8 + k;
        float t0 = acc0[k] * inv0 + b1[c];
        float t1 = acc1[k] * inv1 + b1[HID + c];
        v0[k] = 0.5f * t0 * (1.f + erff(t0 * 0.70710678118654752f));
        v1[k] = 0.5f * t1 * (1.f + erff(t1 * 0.70710678118654752f));
    }
    __half* outp = g_A2h + (size_t)d * F1 + lane * 8;
    uint4 pk0, pk1;
    {
        __half2 a = __floats2half2_rn(v0[0], v0[1]);
        __half2 b = __floats2half2_rn(v0[2], v0[3]);
        __half2 c = __floats2half2_rn(v0[4], v0[5]);
        __half2 e = __floats2half2_rn(v0[6], v0[7]);
        pk0.x = *(uint32_t*)&a; pk0.y = *(uint32_t*)&b;
        pk0.z = *(uint32_t*)&c; pk0.w = *(uint32_t*)&e;
        __half2 a1 = __floats2half2_rn(v1[0], v1[1]);
        __half2 b1h = __floats2half2_rn(v1[2], v1[3]);
        __half2 c1 = __floats2half2_rn(v1[4], v1[5]);
        __half2 e1 = __floats2half2_rn(v1[6], v1[7]);
        pk1.x = *(uint32_t*)&a1; pk1.y = *(uint32_t*)&b1h;
        pk1.z = *(uint32_t*)&c1; pk1.w = *(uint32_t*)&e1;
    }
    *(uint4*)(outp) = pk0;
    *(uint4*)(outp + HID) = pk1;
}

// ---------------- layer-2 aggregation: warp per dst, 4-edge unroll ----------------
__global__ void agg2_kernel(const float* __restrict__ b2, float* __restrict__ out) {
    int d = (blockIdx.x * blockDim.x + threadIdx.x) >> 5;
    int lane = threadIdx.x & 31;
    if (d >= NT) return;
    int beg = g_off[d], end = g_off[d + 1];
    float adh = g_ad2[d];

    float acc[8] = {0.f, 0.f, 0.f, 0.f, 0.f, 0.f, 0.f, 0.f};
    float denom = 0.f;
    int j = beg;
    for (; j + 3 < end; j += 4) {
        int s0 = g_srcidx[j];
        int s1 = g_srcidx[j + 1];
        int s2 = g_srcidx[j + 2];
        int s3 = g_srcidx[j + 3];
        float e0 = g_as2[s0] + adh;
        float e1 = g_as2[s1] + adh;
        float e2 = g_as2[s2] + adh;
        float e3 = g_as2[s3] + adh;
        uint4 r0 = *(const uint4*)(g_xh2 + (size_t)s0 * FOUT + lane * 8);
        uint4 r1 = *(const uint4*)(g_xh2 + (size_t)s1 * FOUT + lane * 8);
        uint4 r2 = *(const uint4*)(g_xh2 + (size_t)s2 * FOUT + lane * 8);
        uint4 r3 = *(const uint4*)(g_xh2 + (size_t)s3 * FOUT + lane * 8);
        float ex0 = __expf(lrelu(e0));
        float ex1 = __expf(lrelu(e1));
        float ex2 = __expf(lrelu(e2));
        float ex3 = __expf(lrelu(e3));
        denom += (ex0 + ex1) + (ex2 + ex3);
        acc8(acc, r0, ex0);
        acc8(acc, r1, ex1);
        acc8(acc, r2, ex2);
        acc8(acc, r3, ex3);
    }
    for (; j < end; j++) {
        int s0 = g_srcidx[j];
        float ex0 = __expf(lrelu(g_as2[s0] + adh));
        denom += ex0;
        uint4 r0 = *(const uint4*)(g_xh2 + (size_t)s0 * FOUT + lane * 8);
        acc8(acc, r0, ex0);
    }
    float inv = 1.f / (denom + 1e-16f);
    float* outp = out + (size_t)d * FOUT + lane * 8;
    float4 o0 = make_float4(acc[0] * inv + b2[lane * 8 + 0],
                            acc[1] * inv + b2[lane * 8 + 1],
                            acc[2] * inv + b2[lane * 8 + 2],
                            acc[3] * inv + b2[lane * 8 + 3]);
    float4 o1 = make_float4(acc[4] * inv + b2[lane * 8 + 4],
                            acc[5] * inv + b2[lane * 8 + 5],
                            acc[6] * inv + b2[lane * 8 + 6],
                            acc[7] * inv + b2[lane * 8 + 7]);
    *(float4*)(outp) = o0;
    *(float4*)(outp + 4) = o1;
}

// ---------------- launch ----------------
extern "C" void kernel_launch(void* const* d_in, const int* in_sizes, int n_in,
                              void* d_out, int out_size) {
    const float* x        = (const float*)d_in[0];
    const int*   ei       = (const int*)  d_in[1];
    const float* W1       = (const float*)d_in[2];
    const float* att_src1 = (const float*)d_in[3];
    const float* att_dst1 = (const float*)d_in[4];
    const float* b1       = (const float*)d_in[5];
    const float* W2       = (const float*)d_in[6];
    const float* att_src2 = (const float*)d_in[7];
    const float* att_dst2 = (const float*)d_in[8];
    const float* b2       = (const float*)d_in[9];
    float* out = (float*)d_out;

    __half *p_xh1, *p_xh2, *p_A1h, *p_A2h, *p_Wt1h, *p_Wt2h;
    cudaGetSymbolAddress((void**)&p_xh1,  g_xh1);
    cudaGetSymbolAddress((void**)&p_xh2,  g_xh2);
    cudaGetSymbolAddress((void**)&p_A1h,  g_A1h);
    cudaGetSymbolAddress((void**)&p_A2h,  g_A2h);
    cudaGetSymbolAddress((void**)&p_Wt1h, g_Wt1h);
    cudaGetSymbolAddress((void**)&p_Wt2h, g_Wt2h);

    static cudaStream_t s2 = nullptr;
    static cudaEvent_t evFork = nullptr, evJoin = nullptr;
    if (!s2) {
        cudaStreamCreateWithFlags(&s2, cudaStreamNonBlocking);
        cudaEventCreateWithFlags(&evFork, cudaEventDisableTiming);
        cudaEventCreateWithFlags(&evJoin, cudaEventDisableTiming);
        cudaFuncSetAttribute(gemm_kernel, cudaFuncAttributeMaxDynamicSharedMemorySize, GEMM_SMEM);
    }

    // ---- fork: CSR build + conv_w2 on s2 ----
    cudaEventRecord(evFork, 0);
    cudaStreamWaitEvent(s2, evFork, 0);
    zero_cnt_kernel<<<(NT + 256) / 256, 256, 0, s2>>>();
    count_kernel<<<(ET + 255) / 256, 256, 0, s2>>>(ei);
    scan_kernel<<<1, 1024, 0, s2>>>();
    fill_kernel<<<(ET + 255) / 256, 256, 0, s2>>>(ei);
    conv_w2_kernel<<<(256 * 512 + 255) / 256, 256, 0, s2>>>(W2);
    cudaEventRecord(evJoin, s2);

    // ---- main: conversions + layer-1 GEMM + alpha1 ----
    conv_x_kernel<<<(NT * 128 + 255) / 256, 256>>>(x);
    conv_w1_kernel<<<(512 * 256 + 255) / 256, 256>>>(W1);
    {
        dim3 grid(F1 / BN, (NT + BM - 1) / BM);
        gemm_kernel<<<grid, 256, GEMM_SMEM>>>(p_A1h, p_Wt1h, p_xh1, NT, F1, 256);
    }
    alpha1_kernel<<<(NT * 32 + 255) / 256, 256>>>(att_src1, att_dst1);

    // ---- join CSR, then aggregate ----
    cudaStreamWaitEvent(0, evJoin, 0);
    agg1_kernel<<<(NT * 32 + 255) / 256, 256>>>(b1);

    // layer-2 GEMM (fp16, K=512)
    {
        dim3 grid(FOUT / BN, (NT + BM - 1) / BM);
        gemm_kernel<<<grid, 256, GEMM_SMEM>>>(p_A2h, p_Wt2h, p_xh2, NT, FOUT, 512);
    }
    alpha2_kernel<<<(NT * 32 + 255) / 256, 256>>>(att_src2, att_dst2);
    agg2_kernel<<<(NT * 32 + 255) / 256, 256>>>(b2, out);
}

// round 15
// speedup vs baseline: 2.3084x; 1.0147x over previous
#include <cuda_runtime.h>
#include <cuda_bf16.h>
#include <cuda_fp16.h>
#include <math.h>
#include <stdint.h>

// ---------------- problem constants ----------------
#define BB   2
#define NN   10000
#define NT   20000           // BB*NN nodes
#define EE   160000          // edges per graph
#define EB   320000          // BB*EE batched edges
#define ET   340000          // EB + NT self loops
#define FIN  256
#define HID  256
#define HH   2
#define F1   512             // HH*HID
#define FOUT 256
#define NEG_SLOPE 0.2f

// ---------------- device scratch ----------------
__device__ __half g_xh1[(size_t)NT * F1];            // fp16 xw1 (gathers + alphas)
__device__ __half g_xh2[(size_t)NT * FOUT];          // fp16 xw2 (gathers + alphas)
__device__ __half g_A1h[(size_t)NT * FIN];           // fp16 x
__device__ __half g_A2h[(size_t)NT * F1];            // fp16 h (layer-2 GEMM input)
__device__ __half g_Wt1h[(size_t)512 * 256];         // W1^T fp16: [n=512][k=256]
__device__ __half g_Wt2h[(size_t)256 * 512];         // W2^T fp16: [n=256][k=512]
__device__ float g_as1[NT * HH];
__device__ float g_ad1[NT * HH];
__device__ float g_as2[NT];
__device__ float g_ad2[NT];
__device__ int   g_cnt[NT + 1];
__device__ int   g_off[NT + 1];
__device__ int   g_srcidx[ET];

// ---------------- helpers ----------------
__device__ __forceinline__ uint32_t smem_u32(const void* p) {
    return (uint32_t)__cvta_generic_to_shared(p);
}
__device__ __forceinline__ void cp16(uint32_t dst, const void* src, int src_sz) {
    asm volatile("cp.async.cg.shared.global [%0], [%1], 16, %2;"
                 :: "r"(dst), "l"(src), "r"(src_sz) : "memory");
}
__device__ __forceinline__ void cp_commit() {
    asm volatile("cp.async.commit_group;" ::: "memory");
}
template <int N>
__device__ __forceinline__ void cp_wait() {
    asm volatile("cp.async.wait_group %0;" :: "n"(N) : "memory");
}
__device__ __forceinline__ void ldm4(uint32_t* r, uint32_t addr) {
    asm volatile("ldmatrix.sync.aligned.m8n8.x4.shared.b16 {%0,%1,%2,%3}, [%4];"
                 : "=r"(r[0]), "=r"(r[1]), "=r"(r[2]), "=r"(r[3]) : "r"(addr));
}
__device__ __forceinline__ void mma16816h(float* c, const uint32_t* a, const uint32_t* b) {
    asm volatile(
        "mma.sync.aligned.m16n8k16.row.col.f32.f16.f16.f32 "
        "{%0,%1,%2,%3}, {%4,%5,%6,%7}, {%8,%9}, {%0,%1,%2,%3};"
        : "+f"(c[0]), "+f"(c[1]), "+f"(c[2]), "+f"(c[3])
        : "r"(a[0]), "r"(a[1]), "r"(a[2]), "r"(a[3]), "r"(b[0]), "r"(b[1]));
}
// XOR swizzle: 64B rows, chunk' = chunk ^ ((row>>1)&3); conflict-free ldmatrix, 16B-aligned
__device__ __forceinline__ uint32_t swz(int row, int cByte) {
    return (uint32_t)(row * 64 + (cByte ^ ((((row >> 1) & 3)) << 4)));
}
__device__ __forceinline__ float lrelu(float e) {
    return e > 0.f ? e : NEG_SLOPE * e;
}
__device__ __forceinline__ void acc8(float* acc, const uint4& r, float ex) {
    float2 a0 = __half22float2(*(const __half2*)&r.x);
    float2 a1 = __half22float2(*(const __half2*)&r.y);
    float2 a2 = __half22float2(*(const __half2*)&r.z);
    float2 a3 = __half22float2(*(const __half2*)&r.w);
    acc[0] += ex * a0.x; acc[1] += ex * a0.y;
    acc[2] += ex * a1.x; acc[3] += ex * a1.y;
    acc[4] += ex * a2.x; acc[5] += ex * a2.y;
    acc[6] += ex * a3.x; acc[7] += ex * a3.y;
}

// ---------------- fp16 mma.sync GEMM, 4-stage cp.async, BKr=32, templated BN ----------------
#define BM 128
#define BKr 32
#define A_TILE_B (128 * 64)              // 8192 bytes (128 rows x 32 halfs, swizzled)
#define NSTG 4

template <int BNT>
__global__ __launch_bounds__(256, 2)
void gemm_kernel(const __half* __restrict__ A,
                 const __half* __restrict__ Bt,
                 __half* __restrict__ Ch, int M, int N, int K) {
    constexpr int B_TILE_B = BNT * 64;           // B tile bytes
    constexpr int STAGE_B = A_TILE_B + B_TILE_B;
    constexpr int NGRP = BNT / 32;               // 16-row B groups per warp tile
    constexpr int NFRG = BNT / 16;               // 8-col fragments per warp tile
    extern __shared__ char sm[];
    const int tid = threadIdx.x;
    const int lane = tid & 31;
    const int wid = tid >> 5;
    const int wm = wid & 3;                      // 4 warps over M (32 rows each)
    const int wn = wid >> 2;                     // 2 warps over N (BNT/2 cols each)
    const int m0 = blockIdx.y * BM;
    const int n0 = blockIdx.x * BNT;
    const uint32_t sbase = smem_u32(sm);

    float acc[2][NFRG][4];
#pragma unroll
    for (int i = 0; i < 2; i++)
#pragma unroll
        for (int j = 0; j < NFRG; j++)
#pragma unroll
            for (int t = 0; t < 4; t++) acc[i][j][t] = 0.f;

    const int lrow = tid >> 1;
    const int cb = (tid & 1) * 32;
    const uint32_t sw0 = swz(lrow, cb);
    const uint32_t sw1 = swz(lrow, cb + 16);
    const int ke = (tid & 1) * 16;
    const __half* gA = A + (size_t)(m0 + lrow) * K;
    const __half* gB = Bt + (size_t)(n0 + (lrow < BNT ? lrow : 0)) * K;
    const int a_ok = (m0 + lrow) < M ? 16 : 0;
    const bool b_do = lrow < BNT;

    const int NIT = K / BKr;

    auto issue = [&](int it) {
        const int s = it & (NSTG - 1);
        const int k0 = it * BKr + ke;
        uint32_t d = sbase + s * STAGE_B;
        cp16(d + sw0,            gA + k0,     a_ok);
        cp16(d + sw1,            gA + k0 + 8, a_ok);
        if (b_do) {
            cp16(d + A_TILE_B + sw0, gB + k0,     16);
            cp16(d + A_TILE_B + sw1, gB + k0 + 8, 16);
        }
        cp_commit();
    };

    issue(0); issue(1); issue(2);

    const int arow = wm * 32 + (lane & 15);
    const int acb = (lane >> 4) * 16;
    const int brow = wn * (BNT / 2) + (lane & 7) + ((lane >> 4) << 3);
    const int bcb = ((lane >> 3) & 1) * 16;

    for (int it = 0; it < NIT; it++) {
        const int s = it & (NSTG - 1);
        cp_wait<NSTG - 2>();
        __syncthreads();
        if (it + 3 < NIT) issue(it + 3); else cp_commit();

        const uint32_t base = sbase + s * STAGE_B;
#pragma unroll
        for (int k16 = 0; k16 < 2; k16++) {
            const int kc = acb + k16 * 32;
            uint32_t a[2][4];
#pragma unroll
            for (int mf = 0; mf < 2; mf++)
                ldm4(a[mf], base + swz(arow + mf * 16, kc));
            const int kb = bcb + k16 * 32;
#pragma unroll
            for (int ng = 0; ng < NGRP; ng++) {
                uint32_t b[4];
                ldm4(b, base + A_TILE_B + swz(brow + ng * 16, kb));
#pragma unroll
                for (int mf = 0; mf < 2; mf++) {
#pragma unroll
                    for (int t = 0; t < 2; t++)
                        mma16816h(acc[mf][ng * 2 + t], a[mf], b + 2 * t);
                }
            }
        }
    }

#pragma unroll
    for (int mf = 0; mf < 2; mf++) {
        const int mA = m0 + wm * 32 + mf * 16 + (lane >> 2);
        const int mB = mA + 8;
#pragma unroll
        for (int nf = 0; nf < NFRG; nf++) {
            const int n = n0 + wn * (BNT / 2) + nf * 8 + (lane & 3) * 2;
            const float* c = acc[mf][nf];
            if (mA < M) *(__half2*)(Ch + (size_t)mA * N + n) = __floats2half2_rn(c[0], c[1]);
            if (mB < M) *(__half2*)(Ch + (size_t)mB * N + n) = __floats2half2_rn(c[2], c[3]);
        }
    }
}

#define GEMM_SMEM_128 (NSTG * (A_TILE_B + 128 * 64))   // 65536
#define GEMM_SMEM_64  (NSTG * (A_TILE_B + 64 * 64))    // 49152

// ---------------- conversion kernels ----------------
__global__ void conv_x_kernel(const float* __restrict__ x) {
    int i = blockIdx.x * blockDim.x + threadIdx.x;
    if (i >= NT * 128) return;
    int row = i >> 7;
    int c2 = (i & 127) << 1;
    float2 f = *(const float2*)(x + (size_t)row * FIN + c2);
    *(__half2*)(g_A1h + (size_t)row * FIN + c2) = __floats2half2_rn(f.x, f.y);
}

__global__ void conv_w1_kernel(const float* __restrict__ W1) {
    int i = blockIdx.x * blockDim.x + threadIdx.x;   // over 512*256
    if (i >= 512 * 256) return;
    int n = i >> 8, k = i & 255;
    g_Wt1h[i] = __float2half(W1[(size_t)k * F1 + n]);
}

__global__ void conv_w2_kernel(const float* __restrict__ W2) {
    int i = blockIdx.x * blockDim.x + threadIdx.x;   // over 256*512
    if (i >= 256 * 512) return;
    int n = i >> 9, k = i & 511;
    g_Wt2h[i] = __float2half(W2[(size_t)k * FOUT + n]);
}

// ---------------- edge enumeration ----------------
__device__ __forceinline__ void edge_sd(int j, const int* ei, int& s, int& d) {
    if (j < EB) {
        int b = j / EE;
        int k = j - b * EE;
        s = ei[k]      + b * NN;
        d = ei[EE + k] + b * NN;
    } else {
        s = d = j - EB;
    }
}

// ---------------- alphas: warp per node, fp16 reads ----------------
__global__ void alpha1_kernel(const float* __restrict__ att_src,
                              const float* __restrict__ att_dst) {
    int gid = blockIdx.x * blockDim.x + threadIdx.x;
    int w = gid >> 5;
    int lane = gid & 31;
    if (w >= NT) return;
#pragma unroll
    for (int h = 0; h < HH; h++) {
        uint4 r = *(const uint4*)(g_xh1 + (size_t)w * F1 + h * HID + lane * 8);
        float2 v0 = __half22float2(*(const __half2*)&r.x);
        float2 v1 = __half22float2(*(const __half2*)&r.y);
        float2 v2 = __half22float2(*(const __half2*)&r.z);
        float2 v3 = __half22float2(*(const __half2*)&r.w);
        const float* as = att_src + h * HID + lane * 8;
        const float* ad = att_dst + h * HID + lane * 8;
        float4 s0 = *(const float4*)(as);
        float4 s1 = *(const float4*)(as + 4);
        float4 d0 = *(const float4*)(ad);
        float4 d1 = *(const float4*)(ad + 4);
        float ps = v0.x * s0.x + v0.y * s0.y + v1.x * s0.z + v1.y * s0.w
                 + v2.x * s1.x + v2.y * s1.y + v3.x * s1.z + v3.y * s1.w;
        float pd = v0.x * d0.x + v0.y * d0.y + v1.x * d0.z + v1.y * d0.w
                 + v2.x * d1.x + v2.y * d1.y + v3.x * d1.z + v3.y * d1.w;
#pragma unroll
        for (int o = 16; o > 0; o >>= 1) {
            ps += __shfl_xor_sync(0xffffffffu, ps, o);
            pd += __shfl_xor_sync(0xffffffffu, pd, o);
        }
        if (lane == 0) { g_as1[w * HH + h] = ps; g_ad1[w * HH + h] = pd; }
    }
}

__global__ void alpha2_kernel(const float* __restrict__ att_src,
                              const float* __restrict__ att_dst) {
    int gid = blockIdx.x * blockDim.x + threadIdx.x;
    int w = gid >> 5;
    int lane = gid & 31;
    if (w >= NT) return;
    uint4 r = *(const uint4*)(g_xh2 + (size_t)w * FOUT + lane * 8);
    float2 v0 = __half22float2(*(const __half2*)&r.x);
    float2 v1 = __half22float2(*(const __half2*)&r.y);
    float2 v2 = __half22float2(*(const __half2*)&r.z);
    float2 v3 = __half22float2(*(const __half2*)&r.w);
    const float* as = att_src + lane * 8;
    const float* ad = att_dst + lane * 8;
    float4 s0 = *(const float4*)(as);
    float4 s1 = *(const float4*)(as + 4);
    float4 d0 = *(const float4*)(ad);
    float4 d1 = *(const float4*)(ad + 4);
    float ps = v0.x * s0.x + v0.y * s0.y + v1.x * s0.z + v1.y * s0.w
             + v2.x * s1.x + v2.y * s1.y + v3.x * s1.z + v3.y * s1.w;
    float pd = v0.x * d0.x + v0.y * d0.y + v1.x * d0.z + v1.y * d0.w
             + v2.x * d1.x + v2.y * d1.y + v3.x * d1.z + v3.y * d1.w;
#pragma unroll
    for (int o = 16; o > 0; o >>= 1) {
        ps += __shfl_xor_sync(0xffffffffu, ps, o);
        pd += __shfl_xor_sync(0xffffffffu, pd, o);
    }
    if (lane == 0) { g_as2[w] = ps; g_ad2[w] = pd; }
}

// ---------------- CSR build (forked stream) ----------------
__global__ void zero_cnt_kernel() {
    int i = blockIdx.x * blockDim.x + threadIdx.x;
    if (i <= NT) g_cnt[i] = 0;
}

__global__ void count_kernel(const int* __restrict__ ei) {
    int j = blockIdx.x * blockDim.x + threadIdx.x;
    if (j >= ET) return;
    int s, d;
    edge_sd(j, ei, s, d);
    atomicAdd(&g_cnt[d], 1);
}

__global__ void scan_kernel() {
    __shared__ int warp_base[32];
    int t = threadIdx.x;
    int lane = t & 31, w = t >> 5;
    const int CH = 20;
    int base = t * CH;
    int local[CH];
    int sum = 0;
#pragma unroll
    for (int i = 0; i < CH; i++) {
        int idx = base + i;
        int v = (idx < NT) ? g_cnt[idx] : 0;
        local[i] = v;
        sum += v;
    }
    int inc = sum;
#pragma unroll
    for (int o = 1; o < 32; o <<= 1) {
        int v = __shfl_up_sync(0xffffffffu, inc, o);
        if (lane >= o) inc += v;
    }
    if (lane == 31) warp_base[w] = inc;
    __syncthreads();
    if (t < 32) {
        int v = warp_base[t];
        int wi = v;
#pragma unroll
        for (int o = 1; o < 32; o <<= 1) {
            int u = __shfl_up_sync(0xffffffffu, wi, o);
            if (t >= o) wi += u;
        }
        warp_base[t] = wi - v;
    }
    __syncthreads();
    int run = warp_base[w] + inc - sum;
#pragma unroll
    for (int i = 0; i < CH; i++) {
        int idx = base + i;
        if (idx < NT) { g_off[idx] = run; run += local[i]; }
    }
    if (t == 0) g_off[NT] = ET;
    for (int i = t; i < NT + 1; i += 1024) g_cnt[i] = 0;
}

__global__ void fill_kernel(const int* __restrict__ ei) {
    int j = blockIdx.x * blockDim.x + threadIdx.x;
    if (j >= ET) return;
    int s, d;
    edge_sd(j, ei, s, d);
    int pos = atomicAdd(&g_cnt[d], 1);
    g_srcidx[g_off[d] + pos] = s;
}

// ---------------- layer-1 aggregation: warp per dst, BOTH heads, 2-edge unroll ----------------
__global__ void agg1_kernel(const float* __restrict__ b1) {
    int d = (blockIdx.x * blockDim.x + threadIdx.x) >> 5;
    int lane = threadIdx.x & 31;
    if (d >= NT) return;
    int beg = g_off[d], end = g_off[d + 1];
    float2 ad = *(const float2*)(g_ad1 + d * 2);

    float acc0[8] = {0.f, 0.f, 0.f, 0.f, 0.f, 0.f, 0.f, 0.f};
    float acc1[8] = {0.f, 0.f, 0.f, 0.f, 0.f, 0.f, 0.f, 0.f};
    float den0 = 0.f, den1 = 0.f;
    int j = beg;
    for (; j + 1 < end; j += 2) {
        int s0 = g_srcidx[j];
        int s1 = g_srcidx[j + 1];
        float2 as0 = *(const float2*)(g_as1 + s0 * 2);
        float2 as1v = *(const float2*)(g_as1 + s1 * 2);
        const __half* p0 = g_xh1 + (size_t)s0 * F1 + lane * 8;
        const __half* p1 = g_xh1 + (size_t)s1 * F1 + lane * 8;
        uint4 rA0 = *(const uint4*)(p0);
        uint4 rB0 = *(const uint4*)(p0 + HID);
        uint4 rA1 = *(const uint4*)(p1);
        uint4 rB1 = *(const uint4*)(p1 + HID);
        float ex00 = __expf(lrelu(as0.x + ad.x));
        float ex01 = __expf(lrelu(as0.y + ad.y));
        float ex10 = __expf(lrelu(as1v.x + ad.x));
        float ex11 = __expf(lrelu(as1v.y + ad.y));
        den0 += ex00 + ex10;
        den1 += ex01 + ex11;
        acc8(acc0, rA0, ex00);
        acc8(acc1, rB0, ex01);
        acc8(acc0, rA1, ex10);
        acc8(acc1, rB1, ex11);
    }
    if (j < end) {
        int s0 = g_srcidx[j];
        float2 as0 = *(const float2*)(g_as1 + s0 * 2);
        const __half* p0 = g_xh1 + (size_t)s0 * F1 + lane * 8;
        uint4 rA0 = *(const uint4*)(p0);
        uint4 rB0 = *(const uint4*)(p0 + HID);
        float ex00 = __expf(lrelu(as0.x + ad.x));
        float ex01 = __expf(lrelu(as0.y + ad.y));
        den0 += ex00;
        den1 += ex01;
        acc8(acc0, rA0, ex00);
        acc8(acc1, rB0, ex01);
    }
    float inv0 = 1.f / (den0 + 1e-16f);
    float inv1 = 1.f / (den1 + 1e-16f);
    float v0[8], v1[8];
#pragma unroll
    for (int k = 0; k < 8; k++) {
        int c = lane * 8 + k;
        float t0 = acc0[k] * inv0 + b1[c];
        float t1 = acc1[k] * inv1 + b1[HID + c];
        v0[k] = 0.5f * t0 * (1.f + erff(t0 * 0.70710678118654752f));
        v1[k] = 0.5f * t1 * (1.f + erff(t1 * 0.70710678118654752f));
    }
    __half* outp = g_A2h + (size_t)d * F1 + lane * 8;
    uint4 pk0, pk1;
    {
        __half2 a = __floats2half2_rn(v0[0], v0[1]);
        __half2 b = __floats2half2_rn(v0[2], v0[3]);
        __half2 c = __floats2half2_rn(v0[4], v0[5]);
        __half2 e = __floats2half2_rn(v0[6], v0[7]);
        pk0.x = *(uint32_t*)&a; pk0.y = *(uint32_t*)&b;
        pk0.z = *(uint32_t*)&c; pk0.w = *(uint32_t*)&e;
        __half2 a1 = __floats2half2_rn(v1[0], v1[1]);
        __half2 b1h = __floats2half2_rn(v1[2], v1[3]);
        __half2 c1 = __floats2half2_rn(v1[4], v1[5]);
        __half2 e1 = __floats2half2_rn(v1[6], v1[7]);
        pk1.x = *(uint32_t*)&a1; pk1.y = *(uint32_t*)&b1h;
        pk1.z = *(uint32_t*)&c1; pk1.w = *(uint32_t*)&e1;
    }
    *(uint4*)(outp) = pk0;
    *(uint4*)(outp + HID) = pk1;
}

// ---------------- layer-2 aggregation: warp per dst, 4-edge unroll ----------------
__global__ void agg2_kernel(const float* __restrict__ b2, float* __restrict__ out) {
    int d = (blockIdx.x * blockDim.x + threadIdx.x) >> 5;
    int lane = threadIdx.x & 31;
    if (d >= NT) return;
    int beg = g_off[d], end = g_off[d + 1];
    float adh = g_ad2[d];

    float acc[8] = {0.f, 0.f, 0.f, 0.f, 0.f, 0.f, 0.f, 0.f};
    float denom = 0.f;
    int j = beg;
    for (; j + 3 < end; j += 4) {
        int s0 = g_srcidx[j];
        int s1 = g_srcidx[j + 1];
        int s2 = g_srcidx[j + 2];
        int s3 = g_srcidx[j + 3];
        float e0 = g_as2[s0] + adh;
        float e1 = g_as2[s1] + adh;
        float e2 = g_as2[s2] + adh;
        float e3 = g_as2[s3] + adh;
        uint4 r0 = *(const uint4*)(g_xh2 + (size_t)s0 * FOUT + lane * 8);
        uint4 r1 = *(const uint4*)(g_xh2 + (size_t)s1 * FOUT + lane * 8);
        uint4 r2 = *(const uint4*)(g_xh2 + (size_t)s2 * FOUT + lane * 8);
        uint4 r3 = *(const uint4*)(g_xh2 + (size_t)s3 * FOUT + lane * 8);
        float ex0 = __expf(lrelu(e0));
        float ex1 = __expf(lrelu(e1));
        float ex2 = __expf(lrelu(e2));
        float ex3 = __expf(lrelu(e3));
        denom += (ex0 + ex1) + (ex2 + ex3);
        acc8(acc, r0, ex0);
        acc8(acc, r1, ex1);
        acc8(acc, r2, ex2);
        acc8(acc, r3, ex3);
    }
    for (; j < end; j++) {
        int s0 = g_srcidx[j];
        float ex0 = __expf(lrelu(g_as2[s0] + adh));
        denom += ex0;
        uint4 r0 = *(const uint4*)(g_xh2 + (size_t)s0 * FOUT + lane * 8);
        acc8(acc, r0, ex0);
    }
    float inv = 1.f / (denom + 1e-16f);
    float* outp = out + (size_t)d * FOUT + lane * 8;
    float4 o0 = make_float4(acc[0] * inv + b2[lane * 8 + 0],
                            acc[1] * inv + b2[lane * 8 + 1],
                            acc[2] * inv + b2[lane * 8 + 2],
                            acc[3] * inv + b2[lane * 8 + 3]);
    float4 o1 = make_float4(acc[4] * inv + b2[lane * 8 + 4],
                            acc[5] * inv + b2[lane * 8 + 5],
                            acc[6] * inv + b2[lane * 8 + 6],
                            acc[7] * inv + b2[lane * 8 + 7]);
    *(float4*)(outp) = o0;
    *(float4*)(outp + 4) = o1;
}

// ---------------- launch ----------------
extern "C" void kernel_launch(void* const* d_in, const int* in_sizes, int n_in,
                              void* d_out, int out_size) {
    const float* x        = (const float*)d_in[0];
    const int*   ei       = (const int*)  d_in[1];
    const float* W1       = (const float*)d_in[2];
    const float* att_src1 = (const float*)d_in[3];
    const float* att_dst1 = (const float*)d_in[4];
    const float* b1       = (const float*)d_in[5];
    const float* W2       = (const float*)d_in[6];
    const float* att_src2 = (const float*)d_in[7];
    const float* att_dst2 = (const float*)d_in[8];
    const float* b2       = (const float*)d_in[9];
    float* out = (float*)d_out;

    __half *p_xh1, *p_xh2, *p_A1h, *p_A2h, *p_Wt1h, *p_Wt2h;
    cudaGetSymbolAddress((void**)&p_xh1,  g_xh1);
    cudaGetSymbolAddress((void**)&p_xh2,  g_xh2);
    cudaGetSymbolAddress((void**)&p_A1h,  g_A1h);
    cudaGetSymbolAddress((void**)&p_A2h,  g_A2h);
    cudaGetSymbolAddress((void**)&p_Wt1h, g_Wt1h);
    cudaGetSymbolAddress((void**)&p_Wt2h, g_Wt2h);

    static cudaStream_t s2 = nullptr;
    static cudaEvent_t evFork = nullptr, evJoin = nullptr;
    if (!s2) {
        cudaStreamCreateWithFlags(&s2, cudaStreamNonBlocking);
        cudaEventCreateWithFlags(&evFork, cudaEventDisableTiming);
        cudaEventCreateWithFlags(&evJoin, cudaEventDisableTiming);
        cudaFuncSetAttribute(gemm_kernel<128>, cudaFuncAttributeMaxDynamicSharedMemorySize, GEMM_SMEM_128);
        cudaFuncSetAttribute(gemm_kernel<64>,  cudaFuncAttributeMaxDynamicSharedMemorySize, GEMM_SMEM_64);
    }

    // ---- fork: CSR build + conv_w2 on s2 ----
    cudaEventRecord(evFork, 0);
    cudaStreamWaitEvent(s2, evFork, 0);
    zero_cnt_kernel<<<(NT + 256) / 256, 256, 0, s2>>>();
    count_kernel<<<(ET + 255) / 256, 256, 0, s2>>>(ei);
    scan_kernel<<<1, 1024, 0, s2>>>();
    fill_kernel<<<(ET + 255) / 256, 256, 0, s2>>>(ei);
    conv_w2_kernel<<<(256 * 512 + 255) / 256, 256, 0, s2>>>(W2);
    cudaEventRecord(evJoin, s2);

    // ---- main: conversions + layer-1 GEMM + alpha1 ----
    conv_x_kernel<<<(NT * 128 + 255) / 256, 256>>>(x);
    conv_w1_kernel<<<(512 * 256 + 255) / 256, 256>>>(W1);
    {
        dim3 grid(F1 / 128, (NT + BM - 1) / BM);
        gemm_kernel<128><<<grid, 256, GEMM_SMEM_128>>>(p_A1h, p_Wt1h, p_xh1, NT, F1, 256);
    }
    alpha1_kernel<<<(NT * 32 + 255) / 256, 256>>>(att_src1, att_dst1);

    // ---- join CSR, then aggregate ----
    cudaStreamWaitEvent(0, evJoin, 0);
    agg1_kernel<<<(NT * 32 + 255) / 256, 256>>>(b1);

    // layer-2 GEMM (fp16, K=512, BN=64 to fix wave quantization: 628 blocks)
    {
        dim3 grid(FOUT / 64, (NT + BM - 1) / BM);
        gemm_kernel<64><<<grid, 256, GEMM_SMEM_64>>>(p_A2h, p_Wt2h, p_xh2, NT, FOUT, 512);
    }
    alpha2_kernel<<<(NT * 32 + 255) / 256, 256>>>(att_src2, att_dst2);
    agg2_kernel<<<(NT * 32 + 255) / 256, 256>>>(b2, out);
}

// round 16
// speedup vs baseline: 2.3433x; 1.0151x over previous
#include <cuda_runtime.h>
#include <cuda_bf16.h>
#include <cuda_fp16.h>
#include <math.h>
#include <stdint.h>

// ---------------- problem constants ----------------
#define BB   2
#define NN   10000
#define NT   20000           // BB*NN nodes
#define EE   160000          // edges per graph
#define EB   320000          // BB*EE batched edges
#define ET   340000          // EB + NT self loops
#define FIN  256
#define HID  256
#define HH   2
#define F1   512             // HH*HID
#define FOUT 256
#define NEG_SLOPE 0.2f

// ---------------- device scratch ----------------
__device__ __half g_xh1[(size_t)NT * F1];            // fp16 xw1 (gathers + alphas)
__device__ __half g_xh2[(size_t)NT * FOUT];          // fp16 xw2 (gathers + alphas)
__device__ __half g_A1h[(size_t)NT * FIN];           // fp16 x
__device__ __half g_A2h[(size_t)NT * F1];            // fp16 h (layer-2 GEMM input)
__device__ __half g_Wt1h[(size_t)512 * 256];         // W1^T fp16: [n=512][k=256]
__device__ __half g_Wt2h[(size_t)256 * 512];         // W2^T fp16: [n=256][k=512]
__device__ float g_as1[NT * HH];
__device__ float g_ad1[NT * HH];
__device__ float g_as2[NT];
__device__ float g_ad2[NT];
__device__ int   g_cnt[NT + 1];
__device__ int   g_off[NT + 1];
__device__ int   g_srcidx[ET];

// ---------------- helpers ----------------
__device__ __forceinline__ uint32_t smem_u32(const void* p) {
    return (uint32_t)__cvta_generic_to_shared(p);
}
__device__ __forceinline__ void cp16(uint32_t dst, const void* src, int src_sz) {
    asm volatile("cp.async.cg.shared.global [%0], [%1], 16, %2;"
                 :: "r"(dst), "l"(src), "r"(src_sz) : "memory");
}
__device__ __forceinline__ void cp_commit() {
    asm volatile("cp.async.commit_group;" ::: "memory");
}
template <int N>
__device__ __forceinline__ void cp_wait() {
    asm volatile("cp.async.wait_group %0;" :: "n"(N) : "memory");
}
__device__ __forceinline__ void ldm4(uint32_t* r, uint32_t addr) {
    asm volatile("ldmatrix.sync.aligned.m8n8.x4.shared.b16 {%0,%1,%2,%3}, [%4];"
                 : "=r"(r[0]), "=r"(r[1]), "=r"(r[2]), "=r"(r[3]) : "r"(addr));
}
__device__ __forceinline__ void mma16816h(float* c, const uint32_t* a, const uint32_t* b) {
    asm volatile(
        "mma.sync.aligned.m16n8k16.row.col.f32.f16.f16.f32 "
        "{%0,%1,%2,%3}, {%4,%5,%6,%7}, {%8,%9}, {%0,%1,%2,%3};"
        : "+f"(c[0]), "+f"(c[1]), "+f"(c[2]), "+f"(c[3])
        : "r"(a[0]), "r"(a[1]), "r"(a[2]), "r"(a[3]), "r"(b[0]), "r"(b[1]));
}
// XOR swizzle: 64B rows, chunk' = chunk ^ ((row>>1)&3); conflict-free ldmatrix, 16B-aligned
__device__ __forceinline__ uint32_t swz(int row, int cByte) {
    return (uint32_t)(row * 64 + (cByte ^ ((((row >> 1) & 3)) << 4)));
}
__device__ __forceinline__ float lrelu(float e) {
    return e > 0.f ? e : NEG_SLOPE * e;
}
__device__ __forceinline__ void acc8(float* acc, const uint4& r, float ex) {
    float2 a0 = __half22float2(*(const __half2*)&r.x);
    float2 a1 = __half22float2(*(const __half2*)&r.y);
    float2 a2 = __half22float2(*(const __half2*)&r.z);
    float2 a3 = __half22float2(*(const __half2*)&r.w);
    acc[0] += ex * a0.x; acc[1] += ex * a0.y;
    acc[2] += ex * a1.x; acc[3] += ex * a1.y;
    acc[4] += ex * a2.x; acc[5] += ex * a2.y;
    acc[6] += ex * a3.x; acc[7] += ex * a3.y;
}

// ---------------- fp16 mma.sync GEMM, 4-stage cp.async, BKr=32, templated BN ----------------
#define BM 128
#define BKr 32
#define A_TILE_B (128 * 64)              // 8192 bytes (128 rows x 32 halfs, swizzled)
#define NSTG 4

template <int BNT>
__global__ __launch_bounds__(256, 2)
void gemm_kernel(const __half* __restrict__ A,
                 const __half* __restrict__ Bt,
                 __half* __restrict__ Ch, int M, int N, int K) {
    constexpr int B_TILE_B = BNT * 64;           // B tile bytes
    constexpr int STAGE_B = A_TILE_B + B_TILE_B;
    constexpr int NGRP = BNT / 32;               // 16-row B groups per warp tile
    constexpr int NFRG = BNT / 16;               // 8-col fragments per warp tile
    extern __shared__ char sm[];
    const int tid = threadIdx.x;
    const int lane = tid & 31;
    const int wid = tid >> 5;
    const int wm = wid & 3;                      // 4 warps over M (32 rows each)
    const int wn = wid >> 2;                     // 2 warps over N (BNT/2 cols each)
    const int m0 = blockIdx.y * BM;
    const int n0 = blockIdx.x * BNT;
    const uint32_t sbase = smem_u32(sm);

    float acc[2][NFRG][4];
#pragma unroll
    for (int i = 0; i < 2; i++)
#pragma unroll
        for (int j = 0; j < NFRG; j++)
#pragma unroll
            for (int t = 0; t < 4; t++) acc[i][j][t] = 0.f;

    const int lrow = tid >> 1;
    const int cb = (tid & 1) * 32;
    const uint32_t sw0 = swz(lrow, cb);
    const uint32_t sw1 = swz(lrow, cb + 16);
    const int ke = (tid & 1) * 16;
    const __half* gA = A + (size_t)(m0 + lrow) * K;
    const __half* gB = Bt + (size_t)(n0 + (lrow < BNT ? lrow : 0)) * K;
    const int a_ok = (m0 + lrow) < M ? 16 : 0;
    const bool b_do = lrow < BNT;

    const int NIT = K / BKr;

    auto issue = [&](int it) {
        const int s = it & (NSTG - 1);
        const int k0 = it * BKr + ke;
        uint32_t d = sbase + s * STAGE_B;
        cp16(d + sw0,            gA + k0,     a_ok);
        cp16(d + sw1,            gA + k0 + 8, a_ok);
        if (b_do) {
            cp16(d + A_TILE_B + sw0, gB + k0,     16);
            cp16(d + A_TILE_B + sw1, gB + k0 + 8, 16);
        }
        cp_commit();
    };

    issue(0); issue(1); issue(2);

    const int arow = wm * 32 + (lane & 15);
    const int acb = (lane >> 4) * 16;
    const int brow = wn * (BNT / 2) + (lane & 7) + ((lane >> 4) << 3);
    const int bcb = ((lane >> 3) & 1) * 16;

    for (int it = 0; it < NIT; it++) {
        const int s = it & (NSTG - 1);
        cp_wait<NSTG - 2>();
        __syncthreads();
        if (it + 3 < NIT) issue(it + 3); else cp_commit();

        const uint32_t base = sbase + s * STAGE_B;
#pragma unroll
        for (int k16 = 0; k16 < 2; k16++) {
            const int kc = acb + k16 * 32;
            uint32_t a[2][4];
#pragma unroll
            for (int mf = 0; mf < 2; mf++)
                ldm4(a[mf], base + swz(arow + mf * 16, kc));
            const int kb = bcb + k16 * 32;
#pragma unroll
            for (int ng = 0; ng < NGRP; ng++) {
                uint32_t b[4];
                ldm4(b, base + A_TILE_B + swz(brow + ng * 16, kb));
#pragma unroll
                for (int mf = 0; mf < 2; mf++) {
#pragma unroll
                    for (int t = 0; t < 2; t++)
                        mma16816h(acc[mf][ng * 2 + t], a[mf], b + 2 * t);
                }
            }
        }
    }

#pragma unroll
    for (int mf = 0; mf < 2; mf++) {
        const int mA = m0 + wm * 32 + mf * 16 + (lane >> 2);
        const int mB = mA + 8;
#pragma unroll
        for (int nf = 0; nf < NFRG; nf++) {
            const int n = n0 + wn * (BNT / 2) + nf * 8 + (lane & 3) * 2;
            const float* c = acc[mf][nf];
            if (mA < M) *(__half2*)(Ch + (size_t)mA * N + n) = __floats2half2_rn(c[0], c[1]);
            if (mB < M) *(__half2*)(Ch + (size_t)mB * N + n) = __floats2half2_rn(c[2], c[3]);
        }
    }
}

#define GEMM_SMEM_128 (NSTG * (A_TILE_B + 128 * 64))   // 65536
#define GEMM_SMEM_64  (NSTG * (A_TILE_B + 64 * 64))    // 49152

// ---------------- merged conversion kernel: x -> fp16, W1^T -> fp16 ----------------
#define CVX_N (NT * 128)           // half2 pairs of x
#define CVW1_N (512 * 256)
__global__ void conv_xw1_kernel(const float* __restrict__ x, const float* __restrict__ W1) {
    int i = blockIdx.x * blockDim.x + threadIdx.x;
    if (i < CVX_N) {
        int row = i >> 7;
        int c2 = (i & 127) << 1;
        float2 f = *(const float2*)(x + (size_t)row * FIN + c2);
        *(__half2*)(g_A1h + (size_t)row * FIN + c2) = __floats2half2_rn(f.x, f.y);
    } else {
        int k = i - CVX_N;
        if (k < CVW1_N) {
            int n = k >> 8, kk = k & 255;
            g_Wt1h[k] = __float2half(W1[(size_t)kk * F1 + n]);
        }
    }
}

__global__ void conv_w2_kernel(const float* __restrict__ W2) {
    int i = blockIdx.x * blockDim.x + threadIdx.x;   // over 256*512
    if (i >= 256 * 512) return;
    int n = i >> 9, k = i & 511;
    g_Wt2h[i] = __float2half(W2[(size_t)k * FOUT + n]);
}

// ---------------- edge enumeration ----------------
__device__ __forceinline__ void edge_sd(int j, const int* ei, int& s, int& d) {
    if (j < EB) {
        int b = j / EE;
        int k = j - b * EE;
        s = ei[k]      + b * NN;
        d = ei[EE + k] + b * NN;
    } else {
        s = d = j - EB;
    }
}

// ---------------- alphas: warp per node, fp16 reads ----------------
__global__ void alpha1_kernel(const float* __restrict__ att_src,
                              const float* __restrict__ att_dst) {
    int gid = blockIdx.x * blockDim.x + threadIdx.x;
    int w = gid >> 5;
    int lane = gid & 31;
    if (w >= NT) return;
#pragma unroll
    for (int h = 0; h < HH; h++) {
        uint4 r = *(const uint4*)(g_xh1 + (size_t)w * F1 + h * HID + lane * 8);
        float2 v0 = __half22float2(*(const __half2*)&r.x);
        float2 v1 = __half22float2(*(const __half2*)&r.y);
        float2 v2 = __half22float2(*(const __half2*)&r.z);
        float2 v3 = __half22float2(*(const __half2*)&r.w);
        const float* as = att_src + h * HID + lane * 8;
        const float* ad = att_dst + h * HID + lane * 8;
        float4 s0 = *(const float4*)(as);
        float4 s1 = *(const float4*)(as + 4);
        float4 d0 = *(const float4*)(ad);
        float4 d1 = *(const float4*)(ad + 4);
        float ps = v0.x * s0.x + v0.y * s0.y + v1.x * s0.z + v1.y * s0.w
                 + v2.x * s1.x + v2.y * s1.y + v3.x * s1.z + v3.y * s1.w;
        float pd = v0.x * d0.x + v0.y * d0.y + v1.x * d0.z + v1.y * d0.w
                 + v2.x * d1.x + v2.y * d1.y + v3.x * d1.z + v3.y * d1.w;
#pragma unroll
        for (int o = 16; o > 0; o >>= 1) {
            ps += __shfl_xor_sync(0xffffffffu, ps, o);
            pd += __shfl_xor_sync(0xffffffffu, pd, o);
        }
        if (lane == 0) { g_as1[w * HH + h] = ps; g_ad1[w * HH + h] = pd; }
    }
}

__global__ void alpha2_kernel(const float* __restrict__ att_src,
                              const float* __restrict__ att_dst) {
    int gid = blockIdx.x * blockDim.x + threadIdx.x;
    int w = gid >> 5;
    int lane = gid & 31;
    if (w >= NT) return;
    uint4 r = *(const uint4*)(g_xh2 + (size_t)w * FOUT + lane * 8);
    float2 v0 = __half22float2(*(const __half2*)&r.x);
    float2 v1 = __half22float2(*(const __half2*)&r.y);
    float2 v2 = __half22float2(*(const __half2*)&r.z);
    float2 v3 = __half22float2(*(const __half2*)&r.w);
    const float* as = att_src + lane * 8;
    const float* ad = att_dst + lane * 8;
    float4 s0 = *(const float4*)(as);
    float4 s1 = *(const float4*)(as + 4);
    float4 d0 = *(const float4*)(ad);
    float4 d1 = *(const float4*)(ad + 4);
    float ps = v0.x * s0.x + v0.y * s0.y + v1.x * s0.z + v1.y * s0.w
             + v2.x * s1.x + v2.y * s1.y + v3.x * s1.z + v3.y * s1.w;
    float pd = v0.x * d0.x + v0.y * d0.y + v1.x * d0.z + v1.y * d0.w
             + v2.x * d1.x + v2.y * d1.y + v3.x * d1.z + v3.y * d1.w;
#pragma unroll
    for (int o = 16; o > 0; o >>= 1) {
        ps += __shfl_xor_sync(0xffffffffu, ps, o);
        pd += __shfl_xor_sync(0xffffffffu, pd, o);
    }
    if (lane == 0) { g_as2[w] = ps; g_ad2[w] = pd; }
}

// ---------------- CSR build (forked stream) ----------------
__global__ void zero_cnt_kernel() {
    int i = blockIdx.x * blockDim.x + threadIdx.x;
    if (i <= NT) g_cnt[i] = 0;
}

__global__ void count_kernel(const int* __restrict__ ei) {
    int j = blockIdx.x * blockDim.x + threadIdx.x;
    if (j >= ET) return;
    int s, d;
    edge_sd(j, ei, s, d);
    atomicAdd(&g_cnt[d], 1);
}

__global__ void scan_kernel() {
    __shared__ int warp_base[32];
    int t = threadIdx.x;
    int lane = t & 31, w = t >> 5;
    const int CH = 20;
    int base = t * CH;
    int local[CH];
    int sum = 0;
#pragma unroll
    for (int i = 0; i < CH; i++) {
        int idx = base + i;
        int v = (idx < NT) ? g_cnt[idx] : 0;
        local[i] = v;
        sum += v;
    }
    int inc = sum;
#pragma unroll
    for (int o = 1; o < 32; o <<= 1) {
        int v = __shfl_up_sync(0xffffffffu, inc, o);
        if (lane >= o) inc += v;
    }
    if (lane == 31) warp_base[w] = inc;
    __syncthreads();
    if (t < 32) {
        int v = warp_base[t];
        int wi = v;
#pragma unroll
        for (int o = 1; o < 32; o <<= 1) {
            int u = __shfl_up_sync(0xffffffffu, wi, o);
            if (t >= o) wi += u;
        }
        warp_base[t] = wi - v;
    }
    __syncthreads();
    int run = warp_base[w] + inc - sum;
#pragma unroll
    for (int i = 0; i < CH; i++) {
        int idx = base + i;
        if (idx < NT) { g_off[idx] = run; run += local[i]; }
    }
    if (t == 0) g_off[NT] = ET;
    for (int i = t; i < NT + 1; i += 1024) g_cnt[i] = 0;
}

__global__ void fill_kernel(const int* __restrict__ ei) {
    int j = blockIdx.x * blockDim.x + threadIdx.x;
    if (j >= ET) return;
    int s, d;
    edge_sd(j, ei, s, d);
    int pos = atomicAdd(&g_cnt[d], 1);
    g_srcidx[g_off[d] + pos] = s;
}

// ---------------- layer-1 aggregation: warp per dst, BOTH heads, prefetched 2-edge unroll ----------------
__global__ void agg1_kernel(const float* __restrict__ b1) {
    int d = (blockIdx.x * blockDim.x + threadIdx.x) >> 5;
    int lane = threadIdx.x & 31;
    if (d >= NT) return;
    int beg = g_off[d], end = g_off[d + 1];
    float2 ad = *(const float2*)(g_ad1 + d * 2);

    float acc0[8] = {0.f, 0.f, 0.f, 0.f, 0.f, 0.f, 0.f, 0.f};
    float acc1[8] = {0.f, 0.f, 0.f, 0.f, 0.f, 0.f, 0.f, 0.f};
    float den0 = 0.f, den1 = 0.f;
    int j = beg;
    int s0n = 0, s1n = 0;
    if (j + 1 < end) { s0n = g_srcidx[j]; s1n = g_srcidx[j + 1]; }
    for (; j + 1 < end; j += 2) {
        int s0 = s0n, s1 = s1n;
        if (j + 3 < end) { s0n = g_srcidx[j + 2]; s1n = g_srcidx[j + 3]; }
        float2 as0 = *(const float2*)(g_as1 + s0 * 2);
        float2 as1v = *(const float2*)(g_as1 + s1 * 2);
        const __half* p0 = g_xh1 + (size_t)s0 * F1 + lane * 8;
        const __half* p1 = g_xh1 + (size_t)s1 * F1 + lane * 8;
        uint4 rA0 = *(const uint4*)(p0);
        uint4 rB0 = *(const uint4*)(p0 + HID);
        uint4 rA1 = *(const uint4*)(p1);
        uint4 rB1 = *(const uint4*)(p1 + HID);
        float ex00 = __expf(lrelu(as0.x + ad.x));
        float ex01 = __expf(lrelu(as0.y + ad.y));
        float ex10 = __expf(lrelu(as1v.x + ad.x));
        float ex11 = __expf(lrelu(as1v.y + ad.y));
        den0 += ex00 + ex10;
        den1 += ex01 + ex11;
        acc8(acc0, rA0, ex00);
        acc8(acc1, rB0, ex01);
        acc8(acc0, rA1, ex10);
        acc8(acc1, rB1, ex11);
    }
    if (j < end) {
        int s0 = g_srcidx[j];
        float2 as0 = *(const float2*)(g_as1 + s0 * 2);
        const __half* p0 = g_xh1 + (size_t)s0 * F1 + lane * 8;
        uint4 rA0 = *(const uint4*)(p0);
        uint4 rB0 = *(const uint4*)(p0 + HID);
        float ex00 = __expf(lrelu(as0.x + ad.x));
        float ex01 = __expf(lrelu(as0.y + ad.y));
        den0 += ex00;
        den1 += ex01;
        acc8(acc0, rA0, ex00);
        acc8(acc1, rB0, ex01);
    }
    float inv0 = 1.f / (den0 + 1e-16f);
    float inv1 = 1.f / (den1 + 1e-16f);
    float v0[8], v1[8];
#pragma unroll
    for (int k = 0; k < 8; k++) {
        int c = lane * 8 + k;
        float t0 = acc0[k] * inv0 + b1[c];
        float t1 = acc1[k] * inv1 + b1[HID + c];
        v0[k] = 0.5f * t0 * (1.f + erff(t0 * 0.70710678118654752f));
        v1[k] = 0.5f * t1 * (1.f + erff(t1 * 0.70710678118654752f));
    }
    __half* outp = g_A2h + (size_t)d * F1 + lane * 8;
    uint4 pk0, pk1;
    {
        __half2 a = __floats2half2_rn(v0[0], v0[1]);
        __half2 b = __floats2half2_rn(v0[2], v0[3]);
        __half2 c = __floats2half2_rn(v0[4], v0[5]);
        __half2 e = __floats2half2_rn(v0[6], v0[7]);
        pk0.x = *(uint32_t*)&a; pk0.y = *(uint32_t*)&b;
        pk0.z = *(uint32_t*)&c; pk0.w = *(uint32_t*)&e;
        __half2 a1 = __floats2half2_rn(v1[0], v1[1]);
        __half2 b1h = __floats2half2_rn(v1[2], v1[3]);
        __half2 c1 = __floats2half2_rn(v1[4], v1[5]);
        __half2 e1 = __floats2half2_rn(v1[6], v1[7]);
        pk1.x = *(uint32_t*)&a1; pk1.y = *(uint32_t*)&b1h;
        pk1.z = *(uint32_t*)&c1; pk1.w = *(uint32_t*)&e1;
    }
    *(uint4*)(outp) = pk0;
    *(uint4*)(outp + HID) = pk1;
}

// ---------------- layer-2 aggregation: warp per dst, prefetched 4-edge unroll ----------------
__global__ void agg2_kernel(const float* __restrict__ b2, float* __restrict__ out) {
    int d = (blockIdx.x * blockDim.x + threadIdx.x) >> 5;
    int lane = threadIdx.x & 31;
    if (d >= NT) return;
    int beg = g_off[d], end = g_off[d + 1];
    float adh = g_ad2[d];

    float acc[8] = {0.f, 0.f, 0.f, 0.f, 0.f, 0.f, 0.f, 0.f};
    float denom = 0.f;
    int j = beg;
    int sn[4] = {0, 0, 0, 0};
    if (j + 3 < end) {
        sn[0] = g_srcidx[j];     sn[1] = g_srcidx[j + 1];
        sn[2] = g_srcidx[j + 2]; sn[3] = g_srcidx[j + 3];
    }
    for (; j + 3 < end; j += 4) {
        int s0 = sn[0], s1 = sn[1], s2 = sn[2], s3 = sn[3];
        if (j + 7 < end) {
            sn[0] = g_srcidx[j + 4]; sn[1] = g_srcidx[j + 5];
            sn[2] = g_srcidx[j + 6]; sn[3] = g_srcidx[j + 7];
        }
        float e0 = g_as2[s0] + adh;
        float e1 = g_as2[s1] + adh;
        float e2 = g_as2[s2] + adh;
        float e3 = g_as2[s3] + adh;
        uint4 r0 = *(const uint4*)(g_xh2 + (size_t)s0 * FOUT + lane * 8);
        uint4 r1 = *(const uint4*)(g_xh2 + (size_t)s1 * FOUT + lane * 8);
        uint4 r2 = *(const uint4*)(g_xh2 + (size_t)s2 * FOUT + lane * 8);
        uint4 r3 = *(const uint4*)(g_xh2 + (size_t)s3 * FOUT + lane * 8);
        float ex0 = __expf(lrelu(e0));
        float ex1 = __expf(lrelu(e1));
        float ex2 = __expf(lrelu(e2));
        float ex3 = __expf(lrelu(e3));
        denom += (ex0 + ex1) + (ex2 + ex3);
        acc8(acc, r0, ex0);
        acc8(acc, r1, ex1);
        acc8(acc, r2, ex2);
        acc8(acc, r3, ex3);
    }
    for (; j < end; j++) {
        int s0 = g_srcidx[j];
        float ex0 = __expf(lrelu(g_as2[s0] + adh));
        denom += ex0;
        uint4 r0 = *(const uint4*)(g_xh2 + (size_t)s0 * FOUT + lane * 8);
        acc8(acc, r0, ex0);
    }
    float inv = 1.f / (denom + 1e-16f);
    float* outp = out + (size_t)d * FOUT + lane * 8;
    float4 o0 = make_float4(acc[0] * inv + b2[lane * 8 + 0],
                            acc[1] * inv + b2[lane * 8 + 1],
                            acc[2] * inv + b2[lane * 8 + 2],
                            acc[3] * inv + b2[lane * 8 + 3]);
    float4 o1 = make_float4(acc[4] * inv + b2[lane * 8 + 4],
                            acc[5] * inv + b2[lane * 8 + 5],
                            acc[6] * inv + b2[lane * 8 + 6],
                            acc[7] * inv + b2[lane * 8 + 7]);
    *(float4*)(outp) = o0;
    *(float4*)(outp + 4) = o1;
}

// ---------------- launch ----------------
extern "C" void kernel_launch(void* const* d_in, const int* in_sizes, int n_in,
                              void* d_out, int out_size) {
    const float* x        = (const float*)d_in[0];
    const int*   ei       = (const int*)  d_in[1];
    const float* W1       = (const float*)d_in[2];
    const float* att_src1 = (const float*)d_in[3];
    const float* att_dst1 = (const float*)d_in[4];
    const float* b1       = (const float*)d_in[5];
    const float* W2       = (const float*)d_in[6];
    const float* att_src2 = (const float*)d_in[7];
    const float* att_dst2 = (const float*)d_in[8];
    const float* b2       = (const float*)d_in[9];
    float* out = (float*)d_out;

    __half *p_xh1, *p_xh2, *p_A1h, *p_A2h, *p_Wt1h, *p_Wt2h;
    cudaGetSymbolAddress((void**)&p_xh1,  g_xh1);
    cudaGetSymbolAddress((void**)&p_xh2,  g_xh2);
    cudaGetSymbolAddress((void**)&p_A1h,  g_A1h);
    cudaGetSymbolAddress((void**)&p_A2h,  g_A2h);
    cudaGetSymbolAddress((void**)&p_Wt1h, g_Wt1h);
    cudaGetSymbolAddress((void**)&p_Wt2h, g_Wt2h);

    static cudaStream_t s2 = nullptr;
    static cudaEvent_t evFork = nullptr, evJoin = nullptr;
    if (!s2) {
        cudaStreamCreateWithFlags(&s2, cudaStreamNonBlocking);
        cudaEventCreateWithFlags(&evFork, cudaEventDisableTiming);
        cudaEventCreateWithFlags(&evJoin, cudaEventDisableTiming);
        cudaFuncSetAttribute(gemm_kernel<128>, cudaFuncAttributeMaxDynamicSharedMemorySize, GEMM_SMEM_128);
        cudaFuncSetAttribute(gemm_kernel<64>,  cudaFuncAttributeMaxDynamicSharedMemorySize, GEMM_SMEM_64);
    }

    // ---- fork: CSR build + conv_w2 on s2 ----
    cudaEventRecord(evFork, 0);
    cudaStreamWaitEvent(s2, evFork, 0);
    zero_cnt_kernel<<<(NT + 256) / 256, 256, 0, s2>>>();
    count_kernel<<<(ET + 255) / 256, 256, 0, s2>>>(ei);
    scan_kernel<<<1, 1024, 0, s2>>>();
    fill_kernel<<<(ET + 255) / 256, 256, 0, s2>>>(ei);
    conv_w2_kernel<<<(256 * 512 + 255) / 256, 256, 0, s2>>>(W2);
    cudaEventRecord(evJoin, s2);

    // ---- main: merged conversion + layer-1 GEMM + alpha1 ----
    conv_xw1_kernel<<<(CVX_N + CVW1_N + 255) / 256, 256>>>(x, W1);
    {
        dim3 grid(F1 / 128, (NT + BM - 1) / BM);
        gemm_kernel<128><<<grid, 256, GEMM_SMEM_128>>>(p_A1h, p_Wt1h, p_xh1, NT, F1, 256);
    }
    alpha1_kernel<<<(NT * 32 + 255) / 256, 256>>>(att_src1, att_dst1);

    // ---- join CSR, then aggregate ----
    cudaStreamWaitEvent(0, evJoin, 0);
    agg1_kernel<<<(NT * 32 + 255) / 256, 256>>>(b1);

    // layer-2 GEMM (fp16, K=512, BN=64: 628 blocks, tight waves)
    {
        dim3 grid(FOUT / 64, (NT + BM - 1) / BM);
        gemm_kernel<64><<<grid, 256, GEMM_SMEM_64>>>(p_A2h, p_Wt2h, p_xh2, NT, FOUT, 512);
    }
    alpha2_kernel<<<(NT * 32 + 255) / 256, 256>>>(att_src2, att_dst2);
    agg2_kernel<<<(NT * 32 + 255) / 256, 256>>>(b2, out);
}